// round 10
// baseline (speedup 1.0000x reference)
#include <cuda_runtime.h>
#include <cuda_bf16.h>
#include <math.h>
#include <cstdint>

#define BATCH 4
#define SEQ   4096
#define EMB   1024
#define HDIM  128

// ---------------------------------------------------------------------------
// scratch (allocation-free: __device__ globals) — all bf16 hi/lo split pairs
// ---------------------------------------------------------------------------
__device__ __nv_bfloat16 g_Qhi[(size_t)BATCH * SEQ * HDIM];
__device__ __nv_bfloat16 g_Qlo[(size_t)BATCH * SEQ * HDIM];
__device__ __nv_bfloat16 g_Khi[(size_t)BATCH * SEQ * HDIM];
__device__ __nv_bfloat16 g_Klo[(size_t)BATCH * SEQ * HDIM];
__device__ __nv_bfloat16 g_Vhi[(size_t)BATCH * SEQ * HDIM];
__device__ __nv_bfloat16 g_Vlo[(size_t)BATCH * SEQ * HDIM];
// split weights: [which][HDIM][EMB], which: 0=K,1=Q,2=V
__device__ __nv_bfloat16 g_Whi[3 * HDIM * EMB];
__device__ __nv_bfloat16 g_Wlo[3 * HDIM * EMB];
// split-K attention partials (numerator O, running max m, running sum l)
__device__ float g_O0[(size_t)BATCH * SEQ * HDIM];
__device__ float g_O1[(size_t)BATCH * SEQ * HDIM];
__device__ float g_O2[(size_t)BATCH * SEQ * HDIM];
__device__ float g_Mp[3][BATCH * SEQ];
__device__ float g_Lp[3][BATCH * SEQ];

// ===========================================================================
// mma.sync / ldmatrix / cp.async helpers (baseline PTX, no 'a' features)
// ===========================================================================
__device__ __forceinline__ uint32_t smem_to_u32(const void* p) {
    uint32_t a;
    asm("{ .reg .u64 t; cvta.to.shared.u64 t, %1; cvt.u32.u64 %0, t; }"
        : "=r"(a) : "l"(p));
    return a;
}

__device__ __forceinline__ void ldsm_x4(uint32_t addr,
    uint32_t& r0, uint32_t& r1, uint32_t& r2, uint32_t& r3) {
    asm volatile("ldmatrix.sync.aligned.m8n8.x4.shared.b16 {%0,%1,%2,%3}, [%4];"
        : "=r"(r0), "=r"(r1), "=r"(r2), "=r"(r3) : "r"(addr));
}

__device__ __forceinline__ void ldsm_x4_t(uint32_t addr,
    uint32_t& r0, uint32_t& r1, uint32_t& r2, uint32_t& r3) {
    asm volatile("ldmatrix.sync.aligned.m8n8.x4.trans.shared.b16 {%0,%1,%2,%3}, [%4];"
        : "=r"(r0), "=r"(r1), "=r"(r2), "=r"(r3) : "r"(addr));
}

__device__ __forceinline__ void mma_bf16(float& c0, float& c1, float& c2, float& c3,
    uint32_t a0, uint32_t a1, uint32_t a2, uint32_t a3, uint32_t b0, uint32_t b1) {
    asm volatile(
        "mma.sync.aligned.m16n8k16.row.col.f32.bf16.bf16.f32 "
        "{%0,%1,%2,%3}, {%4,%5,%6,%7}, {%8,%9}, {%0,%1,%2,%3};"
        : "+f"(c0), "+f"(c1), "+f"(c2), "+f"(c3)
        : "r"(a0), "r"(a1), "r"(a2), "r"(a3), "r"(b0), "r"(b1));
}

#define CP_ASYNC16(dst, src) \
    asm volatile("cp.async.cg.shared.global [%0], [%1], 16;" :: "r"(dst), "l"(src))
#define CP_COMMIT()  asm volatile("cp.async.commit_group;" ::: "memory")
#define CP_WAIT0()   asm volatile("cp.async.wait_group 0;" ::: "memory")
#define CP_WAIT1()   asm volatile("cp.async.wait_group 1;" ::: "memory")

// base-2 exp via MUFU (big-negative -> 0)
__device__ __forceinline__ float ex2(float x) {
    float y;
    asm("ex2.approx.f32 %0, %1;" : "=f"(y) : "f"(x));
    return y;
}

// pack two floats into bf16x2 hi + residual lo
__device__ __forceinline__ void split2(float x0, float x1, uint32_t& hi, uint32_t& lo) {
    __nv_bfloat16 h0 = __float2bfloat16(x0);
    __nv_bfloat16 h1 = __float2bfloat16(x1);
    __nv_bfloat16 g0 = __float2bfloat16(x0 - __bfloat162float(h0));
    __nv_bfloat16 g1 = __float2bfloat16(x1 - __bfloat162float(h1));
    hi = (uint32_t)__bfloat16_as_ushort(h0) | ((uint32_t)__bfloat16_as_ushort(h1) << 16);
    lo = (uint32_t)__bfloat16_as_ushort(g0) | ((uint32_t)__bfloat16_as_ushort(g1) << 16);
}

// ===========================================================================
// Weight split prepass: W (fp32) -> (hi, lo) bf16
// ===========================================================================
__global__ __launch_bounds__(256) void wsplit_kernel(
    const float* __restrict__ Wk,
    const float* __restrict__ Wq,
    const float* __restrict__ Wv)
{
    int idx = blockIdx.x * 256 + threadIdx.x;
    if (idx >= 3 * HDIM * EMB) return;
    int which = idx >> 17;
    int within = idx & ((HDIM * EMB) - 1);
    const float* W = (which == 0) ? Wk : (which == 1) ? Wq : Wv;
    float w = W[within];
    __nv_bfloat16 hi = __float2bfloat16(w);
    __nv_bfloat16 lo = __float2bfloat16(w - __bfloat162float(hi));
    g_Whi[idx] = hi;
    g_Wlo[idx] = lo;
}

// ===========================================================================
// Projection GEMM via mma.sync bf16-split — best measured (73728 B smem,
// 3 CTAs/SM; synchronous loads hidden by cross-CTA TLP).
// grid (128 m-tiles, 3 heads), 256 threads (8 warps x 16 rows = 128 rows).
// ===========================================================================
#define PR_ROWB 144               // 64 bf16 = 128B + 16B pad
#define PR_AHI  0
#define PR_ALO  18432             // 128*144
#define PR_BHI  36864
#define PR_BLO  55296
#define PR_SMEM 73728

extern __shared__ char dsmem[];

__global__ __launch_bounds__(256) void proj_mma_kernel(const float* __restrict__ x)
{
    char* smem = dsmem;
    uint32_t sb = smem_to_u32(smem);
    const int tid  = threadIdx.x;
    const int lane = tid & 31;
    const int w    = tid >> 5;
    const int m0   = blockIdx.x * 128;
    const int which = blockIdx.y;

    const uint32_t a_off = (uint32_t)(w * 16 + (lane & 15)) * PR_ROWB
                         + (uint32_t)((lane >> 4) << 3) * 2;
    const uint32_t b_off = (uint32_t)((lane & 7) + ((lane >> 4) << 3)) * PR_ROWB
                         + (uint32_t)(((lane >> 3) & 1) << 3) * 2;

    float o[16][4];
#pragma unroll
    for (int t = 0; t < 16; t++)
#pragma unroll
        for (int k = 0; k < 4; k++) o[t][k] = 0.0f;

    const int a_row  = tid >> 1;
    const int a_half = tid & 1;

    for (int e0 = 0; e0 < EMB; e0 += 64) {
        __syncthreads();
        {
            const float* xr = x + (size_t)(m0 + a_row) * EMB + e0 + a_half * 32;
            uint32_t abase = (uint32_t)a_row * PR_ROWB + (uint32_t)(a_half * 32) * 2;
#pragma unroll
            for (int i = 0; i < 8; i++) {
                float4 v = *(const float4*)(xr + i * 4);
                uint32_t h01, l01, h23, l23;
                split2(v.x, v.y, h01, l01);
                split2(v.z, v.w, h23, l23);
                uint32_t off = abase + (uint32_t)(i * 4) * 2;
                *(uint32_t*)(smem + PR_AHI + off)     = h01;
                *(uint32_t*)(smem + PR_AHI + off + 4) = h23;
                *(uint32_t*)(smem + PR_ALO + off)     = l01;
                *(uint32_t*)(smem + PR_ALO + off + 4) = l23;
            }
        }
#pragma unroll
        for (int j = 0; j < 4; j++) {
            int idx = tid + j * 256;
            int row = idx >> 3, c8 = idx & 7;
            size_t gsrc = (size_t)(which * HDIM + row) * EMB + e0 + c8 * 8;
            uint32_t doff = (uint32_t)row * PR_ROWB + (uint32_t)c8 * 16;
            *(uint4*)(smem + PR_BHI + doff) = *(const uint4*)(g_Whi + gsrc);
            *(uint4*)(smem + PR_BLO + doff) = *(const uint4*)(g_Wlo + gsrc);
        }
        __syncthreads();

#pragma unroll
        for (int kk = 0; kk < 4; kk++) {
            uint32_t ah0, ah1, ah2, ah3, al0, al1, al2, al3;
            ldsm_x4(sb + PR_AHI + a_off + kk * 32, ah0, ah1, ah2, ah3);
            ldsm_x4(sb + PR_ALO + a_off + kk * 32, al0, al1, al2, al3);
#pragma unroll
            for (int np = 0; np < 8; np++) {
                uint32_t bh0, bh1, bh2, bh3, bl0, bl1, bl2, bl3;
                uint32_t boff = b_off + (uint32_t)(np * 16) * PR_ROWB + kk * 32;
                ldsm_x4(sb + PR_BHI + boff, bh0, bh1, bh2, bh3);
                ldsm_x4(sb + PR_BLO + boff, bl0, bl1, bl2, bl3);
                int t0 = 2 * np, t1 = t0 + 1;
                mma_bf16(o[t0][0], o[t0][1], o[t0][2], o[t0][3], ah0, ah1, ah2, ah3, bh0, bh1);
                mma_bf16(o[t0][0], o[t0][1], o[t0][2], o[t0][3], ah0, ah1, ah2, ah3, bl0, bl1);
                mma_bf16(o[t0][0], o[t0][1], o[t0][2], o[t0][3], al0, al1, al2, al3, bh0, bh1);
                mma_bf16(o[t1][0], o[t1][1], o[t1][2], o[t1][3], ah0, ah1, ah2, ah3, bh2, bh3);
                mma_bf16(o[t1][0], o[t1][1], o[t1][2], o[t1][3], ah0, ah1, ah2, ah3, bl2, bl3);
                mma_bf16(o[t1][0], o[t1][1], o[t1][2], o[t1][3], al0, al1, al2, al3, bh2, bh3);
            }
        }
    }

    // Q pre-scaled by (1/32)*log2(e) so attention softmax runs in base-2.
    const float scale = (which == 1) ? (0.03125f * 1.44269504f) : 1.0f;
    __nv_bfloat16* dh = (which == 0) ? g_Khi : (which == 1) ? g_Qhi : g_Vhi;
    __nv_bfloat16* dl = (which == 0) ? g_Klo : (which == 1) ? g_Qlo : g_Vlo;
    const int r0 = m0 + w * 16 + (lane >> 2);
    const int r1 = r0 + 8;
#pragma unroll
    for (int nt = 0; nt < 16; nt++) {
        int col = nt * 8 + 2 * (lane & 3);
        uint32_t hi, lo;
        split2(o[nt][0] * scale, o[nt][1] * scale, hi, lo);
        *(uint32_t*)(dh + (size_t)r0 * HDIM + col) = hi;
        *(uint32_t*)(dl + (size_t)r0 * HDIM + col) = lo;
        split2(o[nt][2] * scale, o[nt][3] * scale, hi, lo);
        *(uint32_t*)(dh + (size_t)r1 * HDIM + col) = hi;
        *(uint32_t*)(dl + (size_t)r1 * HDIM + col) = lo;
    }
}

// ===========================================================================
// Split-K flash attention, 8 warps, FA2 key-split halves inside the CTA,
// 3-way key-parity split ACROSS CTAs (kt ≡ rho mod 3), partials to gmem.
// grid (96, 4): bx -> pair p = bx/3, parity rho = bx%3. 2 CTAs/SM (104 KB).
// ===========================================================================
#define AT_ROWB 272               // 128 bf16 = 256B + 16B pad
#define AT_TILE 17408             // 64*272
#define AT_QHI  0
#define AT_QLO  17408
#define AT_KHI  34816
#define AT_KLO  52224
#define AT_VHI  69632
#define AT_VLO  87040
#define AT_SMEM 104448
#define M_INIT  (-1e30f)

__global__ __launch_bounds__(256, 2) void attn_mma_kernel()
{
    char* smem = dsmem;
    uint32_t sb = smem_to_u32(smem);
    const int tid  = threadIdx.x;
    const int lane = tid & 31;
    const int w    = tid >> 5;
    const int wq   = w & 3;           // query-row group (16 rows)
    const int nh   = w >> 2;          // key half: 0 -> [0:32), 1 -> [32:64)
    const int b    = blockIdx.y;
    const int pair = blockIdx.x / 3;
    const int rho  = blockIdx.x % 3;  // key-tile parity (mod 3)
    const int bbase = b * SEQ;

    // ldmatrix lane offsets
    const uint32_t a_off = (uint32_t)(wq * 16 + (lane & 15)) * AT_ROWB
                         + (uint32_t)((lane >> 4) << 3) * 2;
    const uint32_t b_off = (uint32_t)(nh * 32 + (lane & 7) + ((lane >> 4) << 3)) * AT_ROWB
                         + (uint32_t)(((lane >> 3) & 1) << 3) * 2;
    const uint32_t v_off = (uint32_t)(nh * 32 + (lane & 7) + (((lane >> 3) & 1) << 3)) * AT_ROWB
                         + (uint32_t)((lane >> 4) << 3) * 2;
    const int r0 = wq * 16 + (lane >> 2);   // tile-local row (0..63)

    for (int half = 0; half < 2; half++) {
        const int qt = half ? (63 - pair) : pair;

        // ---- stage Q tile (hi/lo) into smem ----
        __syncthreads();
        {
            const size_t gq = (size_t)(bbase + qt * 64) * HDIM;
#pragma unroll
            for (int j = 0; j < 4; j++) {
                int idx = tid + j * 256;
                int row = idx >> 4, c16 = idx & 15;
                uint32_t doff = (uint32_t)row * AT_ROWB + (uint32_t)c16 * 16;
                *(uint4*)(smem + AT_QHI + doff) =
                    *(const uint4*)(g_Qhi + gq + (size_t)row * HDIM + c16 * 8);
                *(uint4*)(smem + AT_QLO + doff) =
                    *(const uint4*)(g_Qlo + gq + (size_t)row * HDIM + c16 * 8);
            }
        }
        __syncthreads();

        float o[16][4];
#pragma unroll
        for (int t = 0; t < 16; t++)
#pragma unroll
            for (int k = 0; k < 4; k++) o[t][k] = 0.0f;
        float m0 = M_INIT, m1 = M_INIT, l0 = 0.0f, l1 = 0.0f;

        for (int kt = rho; kt <= qt; kt += 3) {
            const int grow = bbase + kt * 64;

            // ---- issue K group, then V group (single buffer; previous
            //      iteration's readers all passed the trailing barrier) ----
#pragma unroll
            for (int j = 0; j < 4; j++) {
                int idx = tid + j * 256;
                int row = idx >> 4, c16 = idx & 15;
                uint32_t doff = (uint32_t)row * AT_ROWB + (uint32_t)c16 * 16;
                const size_t gs = (size_t)(grow + row) * HDIM + c16 * 8;
                CP_ASYNC16(sb + AT_KHI + doff, (const void*)(g_Khi + gs));
                CP_ASYNC16(sb + AT_KLO + doff, (const void*)(g_Klo + gs));
            }
            CP_COMMIT();
#pragma unroll
            for (int j = 0; j < 4; j++) {
                int idx = tid + j * 256;
                int row = idx >> 4, c16 = idx & 15;
                uint32_t doff = (uint32_t)row * AT_ROWB + (uint32_t)c16 * 16;
                const size_t gs = (size_t)(grow + row) * HDIM + c16 * 8;
                CP_ASYNC16(sb + AT_VHI + doff, (const void*)(g_Vhi + gs));
                CP_ASYNC16(sb + AT_VLO + doff, (const void*)(g_Vlo + gs));
            }
            CP_COMMIT();

            CP_WAIT1();          // K arrived (V still in flight)
            __syncthreads();

            // ---- S = Q K^T on this warp's 32-key half (3-product split) ----
            float s[4][4];
#pragma unroll
            for (int t = 0; t < 4; t++)
#pragma unroll
                for (int k = 0; k < 4; k++) s[t][k] = 0.0f;

#pragma unroll
            for (int kk = 0; kk < 8; kk++) {
                uint32_t qh0, qh1, qh2, qh3, ql0, ql1, ql2, ql3;
                ldsm_x4(sb + AT_QHI + a_off + kk * 32, qh0, qh1, qh2, qh3);
                ldsm_x4(sb + AT_QLO + a_off + kk * 32, ql0, ql1, ql2, ql3);
#pragma unroll
                for (int np = 0; np < 2; np++) {
                    uint32_t kh0, kh1, kh2, kh3, kl0, kl1, kl2, kl3;
                    uint32_t boff = b_off + (uint32_t)(np * 16) * AT_ROWB + kk * 32;
                    ldsm_x4(sb + AT_KHI + boff, kh0, kh1, kh2, kh3);
                    ldsm_x4(sb + AT_KLO + boff, kl0, kl1, kl2, kl3);
                    int t0 = 2 * np, t1 = t0 + 1;
                    mma_bf16(s[t0][0], s[t0][1], s[t0][2], s[t0][3], qh0, qh1, qh2, qh3, kh0, kh1);
                    mma_bf16(s[t1][0], s[t1][1], s[t1][2], s[t1][3], qh0, qh1, qh2, qh3, kh2, kh3);
                    mma_bf16(s[t0][0], s[t0][1], s[t0][2], s[t0][3], qh0, qh1, qh2, qh3, kl0, kl1);
                    mma_bf16(s[t1][0], s[t1][1], s[t1][2], s[t1][3], qh0, qh1, qh2, qh3, kl2, kl3);
                    mma_bf16(s[t0][0], s[t0][1], s[t0][2], s[t0][3], ql0, ql1, ql2, ql3, kh0, kh1);
                    mma_bf16(s[t1][0], s[t1][1], s[t1][2], s[t1][3], ql0, ql1, ql2, ql3, kh2, kh3);
                }
            }

            // ---- causal mask on diagonal tile ----
            if (kt == qt) {
                const int rr0 = r0;
                const int rr1 = r0 + 8;
#pragma unroll
                for (int nt = 0; nt < 4; nt++) {
                    int c = nh * 32 + nt * 8 + 2 * (lane & 3);
                    if (c     > rr0) s[nt][0] = -INFINITY;
                    if (c + 1 > rr0) s[nt][1] = -INFINITY;
                    if (c     > rr1) s[nt][2] = -INFINITY;
                    if (c + 1 > rr1) s[nt][3] = -INFINITY;
                }
            }

            // ---- online softmax (base-2, independent per key-half) ----
            float rmax0 = -INFINITY, rmax1 = -INFINITY;
#pragma unroll
            for (int nt = 0; nt < 4; nt++) {
                rmax0 = fmaxf(rmax0, fmaxf(s[nt][0], s[nt][1]));
                rmax1 = fmaxf(rmax1, fmaxf(s[nt][2], s[nt][3]));
            }
            rmax0 = fmaxf(rmax0, __shfl_xor_sync(0xffffffffu, rmax0, 1));
            rmax0 = fmaxf(rmax0, __shfl_xor_sync(0xffffffffu, rmax0, 2));
            rmax1 = fmaxf(rmax1, __shfl_xor_sync(0xffffffffu, rmax1, 1));
            rmax1 = fmaxf(rmax1, __shfl_xor_sync(0xffffffffu, rmax1, 2));

            float mn0 = fmaxf(m0, rmax0), mn1 = fmaxf(m1, rmax1);
            float alpha0 = ex2(m0 - mn0), alpha1 = ex2(m1 - mn1);
            m0 = mn0; m1 = mn1;

            float sum0 = 0.0f, sum1 = 0.0f;
#pragma unroll
            for (int nt = 0; nt < 4; nt++) {
                s[nt][0] = ex2(s[nt][0] - mn0);
                s[nt][1] = ex2(s[nt][1] - mn0);
                s[nt][2] = ex2(s[nt][2] - mn1);
                s[nt][3] = ex2(s[nt][3] - mn1);
                sum0 += s[nt][0] + s[nt][1];
                sum1 += s[nt][2] + s[nt][3];
            }
            sum0 += __shfl_xor_sync(0xffffffffu, sum0, 1);
            sum0 += __shfl_xor_sync(0xffffffffu, sum0, 2);
            sum1 += __shfl_xor_sync(0xffffffffu, sum1, 1);
            sum1 += __shfl_xor_sync(0xffffffffu, sum1, 2);
            l0 = l0 * alpha0 + sum0;
            l1 = l1 * alpha1 + sum1;

#pragma unroll
            for (int t = 0; t < 16; t++) {
                o[t][0] *= alpha0; o[t][1] *= alpha0;
                o[t][2] *= alpha1; o[t][3] *= alpha1;
            }

            CP_WAIT0();          // V arrived
            __syncthreads();

            // ---- O += P V over this warp's 32-key range (split) ----
#pragma unroll
            for (int kk2 = 0; kk2 < 2; kk2++) {
                int t0 = 2 * kk2, t1 = t0 + 1;
                uint32_t ah0, ah1, ah2, ah3, al0, al1, al2, al3;
                split2(s[t0][0], s[t0][1], ah0, al0);
                split2(s[t0][2], s[t0][3], ah1, al1);
                split2(s[t1][0], s[t1][1], ah2, al2);
                split2(s[t1][2], s[t1][3], ah3, al3);
#pragma unroll
                for (int np = 0; np < 8; np++) {
                    uint32_t vh0, vh1, vh2, vh3, vl0, vl1, vl2, vl3;
                    uint32_t voff = v_off + (uint32_t)(kk2 * 16) * AT_ROWB + np * 32;
                    ldsm_x4_t(sb + AT_VHI + voff, vh0, vh1, vh2, vh3);
                    ldsm_x4_t(sb + AT_VLO + voff, vl0, vl1, vl2, vl3);
                    int u0 = 2 * np, u1 = u0 + 1;
                    mma_bf16(o[u0][0], o[u0][1], o[u0][2], o[u0][3], ah0, ah1, ah2, ah3, vh0, vh1);
                    mma_bf16(o[u1][0], o[u1][1], o[u1][2], o[u1][3], ah0, ah1, ah2, ah3, vh2, vh3);
                    mma_bf16(o[u0][0], o[u0][1], o[u0][2], o[u0][3], ah0, ah1, ah2, ah3, vl0, vl1);
                    mma_bf16(o[u1][0], o[u1][1], o[u1][2], o[u1][3], ah0, ah1, ah2, ah3, vl2, vl3);
                    mma_bf16(o[u0][0], o[u0][1], o[u0][2], o[u0][3], al0, al1, al2, al3, vh0, vh1);
                    mma_bf16(o[u1][0], o[u1][1], o[u1][2], o[u1][3], al0, al1, al2, al3, vh2, vh3);
                }
            }

            __syncthreads();     // all readers done -> buffer reusable
        }

        // ---- merge the two key-halves' (O, m, l); write UNNORMALIZED
        //      partial (numerator, m, l) for this parity to gmem ----
        float* O1s = (float*)(smem + AT_KHI);           // [64][128] scratch
        float* M1s = (float*)(smem + AT_KHI + 32768);   // [64]
        float* L1s = M1s + 64;                          // [64]
        if (nh == 1) {
#pragma unroll
            for (int nt = 0; nt < 16; nt++) {
                int col = nt * 8 + 2 * (lane & 3);
                *(float2*)(O1s + (r0)     * 128 + col) = make_float2(o[nt][0], o[nt][1]);
                *(float2*)(O1s + (r0 + 8) * 128 + col) = make_float2(o[nt][2], o[nt][3]);
            }
            if ((lane & 3) == 0) {
                M1s[r0] = m0;  M1s[r0 + 8] = m1;
                L1s[r0] = l0;  L1s[r0 + 8] = l1;
            }
        }
        __syncthreads();
        if (nh == 0) {
            float* Op = (rho == 0) ? g_O0 : (rho == 1) ? g_O1 : g_O2;
            float m1a = M1s[r0],     l1a = L1s[r0];
            float m1b = M1s[r0 + 8], l1b = L1s[r0 + 8];
            float Ma = fmaxf(m0, m1a), Mb = fmaxf(m1, m1b);
            float b0a = ex2(m0 - Ma),  b1a = ex2(m1a - Ma);
            float b0b = ex2(m1 - Mb),  b1b = ex2(m1b - Mb);
            float La = l0 * b0a + l1a * b1a;
            float Lb = l1 * b0b + l1b * b1b;
            const int gr0 = bbase + qt * 64 + r0;
            const int gr1 = gr0 + 8;
            if ((lane & 3) == 0) {
                g_Mp[rho][gr0] = Ma;  g_Lp[rho][gr0] = La;
                g_Mp[rho][gr1] = Mb;  g_Lp[rho][gr1] = Lb;
            }
#pragma unroll
            for (int nt = 0; nt < 16; nt++) {
                int col = nt * 8 + 2 * (lane & 3);
                float2 p0 = *(const float2*)(O1s + (r0)     * 128 + col);
                float2 p1 = *(const float2*)(O1s + (r0 + 8) * 128 + col);
                *(float2*)(Op + (size_t)gr0 * HDIM + col) = make_float2(
                    o[nt][0] * b0a + p0.x * b1a,
                    o[nt][1] * b0a + p0.y * b1a);
                *(float2*)(Op + (size_t)gr1 * HDIM + col) = make_float2(
                    o[nt][2] * b0b + p1.x * b1b,
                    o[nt][3] * b0b + p1.y * b1b);
            }
        }
    }
}

// ===========================================================================
// Merge the 3 parity partials: out = sum(O_p * 2^(m_p - M)) / sum(l_p * ...)
// ===========================================================================
__global__ __launch_bounds__(128) void attn_merge_kernel(float* __restrict__ out)
{
    const int row = blockIdx.x;          // 0..16383
    const int c   = threadIdx.x;         // 0..127
    float m0 = g_Mp[0][row], m1 = g_Mp[1][row], m2 = g_Mp[2][row];
    float M  = fmaxf(m0, fmaxf(m1, m2));
    float w0 = ex2(m0 - M), w1 = ex2(m1 - M), w2 = ex2(m2 - M);
    float L  = g_Lp[0][row] * w0 + g_Lp[1][row] * w1 + g_Lp[2][row] * w2;
    size_t off = (size_t)row * HDIM + c;
    out[off] = (g_O0[off] * w0 + g_O1[off] * w1 + g_O2[off] * w2) / L;
}

// ---------------------------------------------------------------------------
extern "C" void kernel_launch(void* const* d_in, const int* in_sizes, int n_in,
                              void* d_out, int out_size)
{
    const float* x  = (const float*)d_in[0];
    const float* Wk = (const float*)d_in[1];
    const float* Wq = (const float*)d_in[2];
    const float* Wv = (const float*)d_in[3];
    float* out = (float*)d_out;

    static bool attr_set = false;
    if (!attr_set) {
        cudaFuncSetAttribute(proj_mma_kernel,
                             cudaFuncAttributeMaxDynamicSharedMemorySize, PR_SMEM);
        cudaFuncSetAttribute(attn_mma_kernel,
                             cudaFuncAttributeMaxDynamicSharedMemorySize, AT_SMEM);
        attr_set = true;
    }

    // 1) split weights to bf16 hi/lo
    wsplit_kernel<<<(3 * HDIM * EMB + 255) / 256, 256>>>(Wk, Wq, Wv);

    // 2) Q/K/V projections on tensor cores (bf16-split), 3 CTAs/SM
    proj_mma_kernel<<<dim3(128, 3), 256, PR_SMEM>>>(x);

    // 3) split-K causal flash attention: 384 CTAs, 2 CTAs/SM
    attn_mma_kernel<<<dim3(96, BATCH), 256, AT_SMEM>>>();

    // 4) merge parity partials
    attn_merge_kernel<<<BATCH * SEQ, 128>>>(out);
}

// round 11
// speedup vs baseline: 1.1185x; 1.1185x over previous
#include <cuda_runtime.h>
#include <math.h>
#include <cstdint>

#define BATCH 4
#define SEQ   4096
#define EMB   1024
#define HDIM  128
#define FULLM 0xffffffffu

// ---------------------------------------------------------------------------
// scratch (allocation-free: __device__ globals) — all tf32-rounded fp32
// ---------------------------------------------------------------------------
// Q, K: [b*SEQ+row][dim], dims pair-permuted within 8-groups ((c,c+4) adjacent)
__device__ float g_Q[(size_t)BATCH * SEQ * HDIM];
__device__ float g_K[(size_t)BATCH * SEQ * HDIM];
// V transposed: [b][dim][seq], keys pair-permuted within 8-groups
__device__ float g_Vt[(size_t)BATCH * HDIM * SEQ];
// W: [which][n][k], k pair-permuted; which: 0=K,1=Q,2=V
__device__ float g_Wp[3 * HDIM * EMB];
// x: [row][k], k pair-permuted, tf32-rounded
__device__ float g_xp[(size_t)BATCH * SEQ * EMB];

// ===========================================================================
// helpers
// ===========================================================================
__device__ __forceinline__ int perm8(int i) { return (i < 4) ? 2 * i : 2 * (i - 4) + 1; }

__device__ __forceinline__ float totf32(float x) {
    uint32_t r;
    asm("cvt.rna.tf32.f32 %0, %1;" : "=r"(r) : "f"(x));
    return __uint_as_float(r);
}

__device__ __forceinline__ void mma_tf32(float& c0, float& c1, float& c2, float& c3,
    float a0, float a1, float a2, float a3, float b0, float b1) {
    asm volatile(
        "mma.sync.aligned.m16n8k8.row.col.f32.tf32.tf32.f32 "
        "{%0,%1,%2,%3}, {%4,%5,%6,%7}, {%8,%9}, {%0,%1,%2,%3};"
        : "+f"(c0), "+f"(c1), "+f"(c2), "+f"(c3)
        : "r"(__float_as_uint(a0)), "r"(__float_as_uint(a1)),
          "r"(__float_as_uint(a2)), "r"(__float_as_uint(a3)),
          "r"(__float_as_uint(b0)), "r"(__float_as_uint(b1)));
}

#define CP_ASYNC16(dst, src) \
    asm volatile("cp.async.cg.shared.global [%0], [%1], 16;" :: "r"(dst), "l"(src))
#define CP_COMMIT()  asm volatile("cp.async.commit_group;" ::: "memory")
#define CP_WAIT0()   asm volatile("cp.async.wait_group 0;" ::: "memory")

__device__ __forceinline__ uint32_t smem_to_u32(const void* p) {
    uint32_t a;
    asm("{ .reg .u64 t; cvta.to.shared.u64 t, %1; cvt.u32.u64 %0, t; }"
        : "=r"(a) : "l"(p));
    return a;
}

__device__ __forceinline__ float ex2(float x) {
    float y;
    asm("ex2.approx.f32 %0, %1;" : "=f"(y) : "f"(x));
    return y;
}

// ===========================================================================
// prep: x and W -> tf32-rounded, k pair-permuted
// ===========================================================================
__global__ __launch_bounds__(256) void xprep_kernel(const float* __restrict__ x)
{
    size_t idx = (size_t)blockIdx.x * 256 + threadIdx.x;
    if (idx >= (size_t)BATCH * SEQ * EMB) return;
    int k = (int)(idx & (EMB - 1));
    size_t row = idx >> 10;
    g_xp[row * EMB + (k & ~7) + perm8(k & 7)] = totf32(x[idx]);
}

__global__ __launch_bounds__(256) void wprep_kernel(
    const float* __restrict__ Wk,
    const float* __restrict__ Wq,
    const float* __restrict__ Wv)
{
    int idx = blockIdx.x * 256 + threadIdx.x;
    if (idx >= 3 * HDIM * EMB) return;
    int which = idx >> 17;
    int within = idx & ((HDIM * EMB) - 1);
    int k = within & (EMB - 1);
    int n = within >> 10;
    const float* W = (which == 0) ? Wk : (which == 1) ? Wq : Wv;
    g_Wp[which * HDIM * EMB + n * EMB + (k & ~7) + perm8(k & 7)] = totf32(W[within]);
}

// ===========================================================================
// Projection GEMM, tf32 single-product.
// grid (128 m-tiles, 3 heads), 256 threads (8 warps x 16 rows).
// smem tiles: x [128][64], W [128][64], row stride 288 B (conflict-free LDS.64)
// ===========================================================================
#define PJ_RS   288
#define PJ_X    0
#define PJ_W    36864
#define PJ_SMEM 73728

extern __shared__ char dsmem[];

__global__ __launch_bounds__(256) void proj_mma_kernel()
{
    char* smem = dsmem;
    const int tid  = threadIdx.x;
    const int lane = tid & 31;
    const int w    = tid >> 5;
    const int m0   = blockIdx.x * 128;
    const int which = blockIdx.y;

    float o[16][4];
#pragma unroll
    for (int t = 0; t < 16; t++)
#pragma unroll
        for (int k = 0; k < 4; k++) o[t][k] = 0.0f;

    const uint32_t a_row0 = (uint32_t)(w * 16 + (lane >> 2)) * PJ_RS + (lane & 3) * 8;
    const uint32_t b_base = (uint32_t)(lane >> 2) * PJ_RS + (lane & 3) * 8;

    for (int e0 = 0; e0 < EMB; e0 += 64) {
        __syncthreads();
        // stage x and W tiles (straight uint4 copies; perm pre-applied in gmem)
#pragma unroll
        for (int j = 0; j < 8; j++) {
            int idx = tid + j * 256;               // 0..2047
            int row = idx >> 4, c16 = idx & 15;
            *(uint4*)(smem + PJ_X + row * PJ_RS + c16 * 16) =
                *(const uint4*)(g_xp + (size_t)(m0 + row) * EMB + e0 + c16 * 4);
            *(uint4*)(smem + PJ_W + row * PJ_RS + c16 * 16) =
                *(const uint4*)(g_Wp + (size_t)(which * HDIM + row) * EMB + e0 + c16 * 4);
        }
        __syncthreads();

#pragma unroll
        for (int st = 0; st < 8; st++) {
            float2 aA = *(const float2*)(smem + PJ_X + a_row0 + st * 32);
            float2 aB = *(const float2*)(smem + PJ_X + a_row0 + 8 * PJ_RS + st * 32);
#pragma unroll
            for (int nt = 0; nt < 16; nt++) {
                float2 b = *(const float2*)(smem + PJ_W + b_base
                                            + (uint32_t)(nt * 8) * PJ_RS + st * 32);
                mma_tf32(o[nt][0], o[nt][1], o[nt][2], o[nt][3],
                         aA.x, aB.x, aA.y, aB.y, b.x, b.y);
            }
        }
    }

    // ---- epilogue ----
    const int r0 = m0 + w * 16 + (lane >> 2);
    const int r1 = r0 + 8;
    if (which == 2) {
        // V: transpose into g_Vt[b][dim][seq], keys pair-permuted
        const int b0i = r0 >> 12, s0 = r0 & 4095;
        const int b1i = r1 >> 12, s1 = r1 & 4095;
        const int sp0 = (s0 & ~7) + perm8(s0 & 7);
        const int sp1 = (s1 & ~7) + perm8(s1 & 7);
#pragma unroll
        for (int nt = 0; nt < 16; nt++) {
            int col = nt * 8 + 2 * (lane & 3);
            g_Vt[((size_t)b0i * HDIM + col)     * SEQ + sp0] = totf32(o[nt][0]);
            g_Vt[((size_t)b0i * HDIM + col + 1) * SEQ + sp0] = totf32(o[nt][1]);
            g_Vt[((size_t)b1i * HDIM + col)     * SEQ + sp1] = totf32(o[nt][2]);
            g_Vt[((size_t)b1i * HDIM + col + 1) * SEQ + sp1] = totf32(o[nt][3]);
        }
    } else {
        // Q (scaled, base-2 softmax) / K: dims pair-permuted
        const float scale = (which == 1) ? (0.03125f * 1.44269504f) : 1.0f;
        float* dst = (which == 1) ? g_Q : g_K;
#pragma unroll
        for (int nt = 0; nt < 16; nt++) {
            int col = nt * 8 + 2 * (lane & 3);
            int p0 = (col & ~7) + perm8(col & 7);
            int p1 = (col & ~7) + perm8((col & 7) + 1);
            dst[(size_t)r0 * HDIM + p0] = totf32(o[nt][0] * scale);
            dst[(size_t)r0 * HDIM + p1] = totf32(o[nt][1] * scale);
            dst[(size_t)r1 * HDIM + p0] = totf32(o[nt][2] * scale);
            dst[(size_t)r1 * HDIM + p1] = totf32(o[nt][3] * scale);
        }
    }
}

// ===========================================================================
// Flash attention, tf32 single-product, 8 warps, FA2 key-split halves
// (independent m/l/O per half, one merge per q-tile).
// grid (32 pairs, 4 batch). BQ=64, BK=64, pair balancing.
// K tile [64 keys][128 dims] RS=544; V^T tile [128 dims][64 keys] RS=288.
// Double-buffered: 2*(34816+36864) = 143360 B, 1 CTA/SM.
// ===========================================================================
#define AK_RS  544
#define AV_RS  288
#define A_K    0
#define A_V    34816
#define A_BUF  71680
#define A_SMEM 143360
#define M_INIT (-1e30f)

__device__ __forceinline__ void prefetch_kv(uint32_t sb_buf, int b, int grow, int kt, int tid)
{
#pragma unroll
    for (int j = 0; j < 8; j++) {
        int idx = tid + j * 256;                 // 0..2047
        int row = idx >> 5, c = idx & 31;        // K: 64 rows x 32 uint4
        CP_ASYNC16(sb_buf + A_K + (uint32_t)row * AK_RS + c * 16,
                   (const void*)(g_K + (size_t)(grow + row) * HDIM + c * 4));
    }
#pragma unroll
    for (int j = 0; j < 8; j++) {
        int idx = tid + j * 256;
        int row = idx >> 4, c = idx & 15;        // V^T: 128 rows x 16 uint4
        CP_ASYNC16(sb_buf + A_V + (uint32_t)row * AV_RS + c * 16,
                   (const void*)(g_Vt + ((size_t)b * HDIM + row) * SEQ + kt * 64 + c * 4));
    }
    CP_COMMIT();
}

__global__ __launch_bounds__(256, 1) void attn_mma_kernel(float* __restrict__ out)
{
    char* smem = dsmem;
    uint32_t sb = smem_to_u32(smem);
    const int tid  = threadIdx.x;
    const int lane = tid & 31;
    const int w    = tid >> 5;
    const int wq   = w & 3;           // query-row group (16 rows)
    const int nh   = w >> 2;          // key half: 0 -> [0:32), 1 -> [32:64)
    const int b    = blockIdx.y;
    const int pair = blockIdx.x;
    const int bbase = b * SEQ;

    const int r0 = wq * 16 + (lane >> 2);        // tile-local row (0..63)
    // P-shuffle lane map (C-frag -> A-frag)
    const int pc = lane & 3;
    const int src_lo = (lane & 28) | (pc >> 1);
    const int src_hi = src_lo | 2;
    const int pe = pc & 1;

    for (int half = 0; half < 2; half++) {
        const int qt = half ? (63 - pair) : pair;
        const int nkt = qt + 1;

        __syncthreads();   // previous half's merge reads done before reuse

        // ---- hoist Q fragments (tf32, dims pair-permuted in gmem) ----
        float qf[16][4];
        {
            const float* q0 = g_Q + (size_t)(bbase + qt * 64 + wq * 16 + (lane >> 2)) * HDIM
                              + (lane & 3) * 2;
#pragma unroll
            for (int st = 0; st < 16; st++) {
                float2 u = *(const float2*)(q0 + st * 8);
                float2 v = *(const float2*)(q0 + 8 * HDIM + st * 8);
                qf[st][0] = u.x; qf[st][1] = v.x; qf[st][2] = u.y; qf[st][3] = v.y;
            }
        }

        float o[16][4];
#pragma unroll
        for (int t = 0; t < 16; t++)
#pragma unroll
            for (int k = 0; k < 4; k++) o[t][k] = 0.0f;
        float m0 = M_INIT, m1 = M_INIT, l0 = 0.0f, l1 = 0.0f;

        prefetch_kv(sb, b, bbase, 0, tid);       // kt=0 -> buf 0

        for (int kt = 0; kt < nkt; kt++) {
            CP_WAIT0();
            __syncthreads();
            if (kt + 1 < nkt)
                prefetch_kv(sb + ((kt + 1) & 1) * A_BUF, b,
                            bbase + (kt + 1) * 64, kt + 1, tid);
            const uint32_t kb = sb + (kt & 1) * A_BUF;

            // ---- S = Q K^T on this warp's 32-key half ----
            float s[4][4];
#pragma unroll
            for (int t = 0; t < 4; t++)
#pragma unroll
                for (int k = 0; k < 4; k++) s[t][k] = 0.0f;

            const uint32_t kfb = kb + A_K + (uint32_t)(nh * 32 + (lane >> 2)) * AK_RS
                               + (lane & 3) * 8;
#pragma unroll
            for (int st = 0; st < 16; st++) {
#pragma unroll
                for (int np = 0; np < 4; np++) {
                    float2 bb = *(const float2*)(smem + (kfb - sb)
                                 + (uint32_t)(np * 8) * AK_RS + st * 32);
                    mma_tf32(s[np][0], s[np][1], s[np][2], s[np][3],
                             qf[st][0], qf[st][1], qf[st][2], qf[st][3], bb.x, bb.y);
                }
            }

            // ---- causal mask on diagonal tile ----
            if (kt == qt) {
                const int rr0 = r0, rr1 = r0 + 8;
#pragma unroll
                for (int nt = 0; nt < 4; nt++) {
                    int c = nh * 32 + nt * 8 + 2 * (lane & 3);
                    if (c     > rr0) s[nt][0] = -INFINITY;
                    if (c + 1 > rr0) s[nt][1] = -INFINITY;
                    if (c     > rr1) s[nt][2] = -INFINITY;
                    if (c + 1 > rr1) s[nt][3] = -INFINITY;
                }
            }

            // ---- online softmax (base-2, independent per key-half) ----
            float rmax0 = -INFINITY, rmax1 = -INFINITY;
#pragma unroll
            for (int nt = 0; nt < 4; nt++) {
                rmax0 = fmaxf(rmax0, fmaxf(s[nt][0], s[nt][1]));
                rmax1 = fmaxf(rmax1, fmaxf(s[nt][2], s[nt][3]));
            }
            rmax0 = fmaxf(rmax0, __shfl_xor_sync(FULLM, rmax0, 1));
            rmax0 = fmaxf(rmax0, __shfl_xor_sync(FULLM, rmax0, 2));
            rmax1 = fmaxf(rmax1, __shfl_xor_sync(FULLM, rmax1, 1));
            rmax1 = fmaxf(rmax1, __shfl_xor_sync(FULLM, rmax1, 2));

            float mn0 = fmaxf(m0, rmax0), mn1 = fmaxf(m1, rmax1);
            float alpha0 = ex2(m0 - mn0), alpha1 = ex2(m1 - mn1);
            m0 = mn0; m1 = mn1;

            float sum0 = 0.0f, sum1 = 0.0f;
#pragma unroll
            for (int nt = 0; nt < 4; nt++) {
                s[nt][0] = ex2(s[nt][0] - mn0);
                s[nt][1] = ex2(s[nt][1] - mn0);
                s[nt][2] = ex2(s[nt][2] - mn1);
                s[nt][3] = ex2(s[nt][3] - mn1);
                sum0 += s[nt][0] + s[nt][1];
                sum1 += s[nt][2] + s[nt][3];
            }
            sum0 += __shfl_xor_sync(FULLM, sum0, 1);
            sum0 += __shfl_xor_sync(FULLM, sum0, 2);
            sum1 += __shfl_xor_sync(FULLM, sum1, 1);
            sum1 += __shfl_xor_sync(FULLM, sum1, 2);
            l0 = l0 * alpha0 + sum0;
            l1 = l1 * alpha1 + sum1;

#pragma unroll
            for (int t = 0; t < 16; t++) {
                o[t][0] *= alpha0; o[t][1] *= alpha0;
                o[t][2] *= alpha1; o[t][3] *= alpha1;
            }

            // ---- O += P V over this warp's 32-key range ----
            const uint32_t vfb = (kb - sb) + A_V + (uint32_t)(lane >> 2) * AV_RS
                               + (nh * 32) * 4 + (lane & 3) * 8;
#pragma unroll
            for (int t = 0; t < 4; t++) {
                // C-frag -> A-frag remap of P via shuffles
                float v0 = __shfl_sync(FULLM, s[t][0], src_lo);
                float v1 = __shfl_sync(FULLM, s[t][1], src_lo);
                float v2 = __shfl_sync(FULLM, s[t][2], src_lo);
                float v3 = __shfl_sync(FULLM, s[t][3], src_lo);
                float h0 = __shfl_sync(FULLM, s[t][0], src_hi);
                float h1 = __shfl_sync(FULLM, s[t][1], src_hi);
                float h2 = __shfl_sync(FULLM, s[t][2], src_hi);
                float h3 = __shfl_sync(FULLM, s[t][3], src_hi);
                float pa0 = totf32(pe ? v1 : v0);
                float pa1 = totf32(pe ? v3 : v2);
                float pa2 = totf32(pe ? h1 : h0);
                float pa3 = totf32(pe ? h3 : h2);
#pragma unroll
                for (int nd = 0; nd < 16; nd++) {
                    float2 bb = *(const float2*)(smem + vfb
                                 + (uint32_t)(nd * 8) * AV_RS + t * 32);
                    mma_tf32(o[nd][0], o[nd][1], o[nd][2], o[nd][3],
                             pa0, pa1, pa2, pa3, bb.x, bb.y);
                }
            }
        }

        // ---- merge the two key-halves' (O, m, l), normalize, store ----
        __syncthreads();   // all smem reads done; reuse buf0 as scratch
        float* O1s = (float*)(smem);                // [64][128]
        float* M1s = (float*)(smem + 32768);        // [64]
        float* L1s = M1s + 64;                      // [64]
        if (nh == 1) {
#pragma unroll
            for (int nt = 0; nt < 16; nt++) {
                int col = nt * 8 + 2 * (lane & 3);
                *(float2*)(O1s + (r0)     * 128 + col) = make_float2(o[nt][0], o[nt][1]);
                *(float2*)(O1s + (r0 + 8) * 128 + col) = make_float2(o[nt][2], o[nt][3]);
            }
            if ((lane & 3) == 0) {
                M1s[r0] = m0;  M1s[r0 + 8] = m1;
                L1s[r0] = l0;  L1s[r0 + 8] = l1;
            }
        }
        __syncthreads();
        if (nh == 0) {
            float m1a = M1s[r0],     l1a = L1s[r0];
            float m1b = M1s[r0 + 8], l1b = L1s[r0 + 8];
            float Ma = fmaxf(m0, m1a), Mb = fmaxf(m1, m1b);
            float b0a = ex2(m0 - Ma),  b1a = ex2(m1a - Ma);
            float b0b = ex2(m1 - Mb),  b1b = ex2(m1b - Mb);
            float invLa = 1.0f / (l0 * b0a + l1a * b1a);
            float invLb = 1.0f / (l1 * b0b + l1b * b1b);
            const int gr0 = bbase + qt * 64 + r0;
            const int gr1 = gr0 + 8;
#pragma unroll
            for (int nt = 0; nt < 16; nt++) {
                int col = nt * 8 + 2 * (lane & 3);
                float2 p0 = *(const float2*)(O1s + (r0)     * 128 + col);
                float2 p1 = *(const float2*)(O1s + (r0 + 8) * 128 + col);
                *(float2*)(out + (size_t)gr0 * HDIM + col) = make_float2(
                    (o[nt][0] * b0a + p0.x * b1a) * invLa,
                    (o[nt][1] * b0a + p0.y * b1a) * invLa);
                *(float2*)(out + (size_t)gr1 * HDIM + col) = make_float2(
                    (o[nt][2] * b0b + p1.x * b1b) * invLb,
                    (o[nt][3] * b0b + p1.y * b1b) * invLb);
            }
        }
    }
}

// ---------------------------------------------------------------------------
extern "C" void kernel_launch(void* const* d_in, const int* in_sizes, int n_in,
                              void* d_out, int out_size)
{
    const float* x  = (const float*)d_in[0];
    const float* Wk = (const float*)d_in[1];
    const float* Wq = (const float*)d_in[2];
    const float* Wv = (const float*)d_in[3];
    float* out = (float*)d_out;

    static bool attr_set = false;
    if (!attr_set) {
        cudaFuncSetAttribute(proj_mma_kernel,
                             cudaFuncAttributeMaxDynamicSharedMemorySize, PJ_SMEM);
        cudaFuncSetAttribute(attn_mma_kernel,
                             cudaFuncAttributeMaxDynamicSharedMemorySize, A_SMEM);
        attr_set = true;
    }

    // 1) prep: x and W -> tf32-rounded, pair-permuted
    xprep_kernel<<<(int)(((size_t)BATCH * SEQ * EMB + 255) / 256), 256>>>(x);
    wprep_kernel<<<(3 * HDIM * EMB + 255) / 256, 256>>>(Wk, Wq, Wv);

    // 2) Q/K/V projections, tf32 single-product tensor-core GEMM
    proj_mma_kernel<<<dim3(128, 3), 256, PJ_SMEM>>>();

    // 3) causal flash attention, tf32 single-product, 8 warps
    attn_mma_kernel<<<dim3(32, BATCH), 256, A_SMEM>>>(out);
}

// round 12
// speedup vs baseline: 1.1606x; 1.0377x over previous
#include <cuda_runtime.h>
#include <math.h>
#include <cstdint>

#define BATCH 4
#define SEQ   4096
#define EMB   1024
#define HDIM  128
#define FULLM 0xffffffffu

// ---------------------------------------------------------------------------
// scratch (allocation-free: __device__ globals) — all tf32-rounded fp32
// ---------------------------------------------------------------------------
// Q, K: [b*SEQ+row][dim], dims pair-permuted within 8-groups ((c,c+4) adjacent)
__device__ float g_Q[(size_t)BATCH * SEQ * HDIM];
__device__ float g_K[(size_t)BATCH * SEQ * HDIM];
// V transposed: [b][dim][seq], keys pair-permuted within 8-groups
__device__ float g_Vt[(size_t)BATCH * HDIM * SEQ];
// W: [which][n][k], k pair-permuted; which: 0=K,1=Q,2=V
__device__ float g_Wp[3 * HDIM * EMB];

// ===========================================================================
// helpers
// ===========================================================================
__device__ __forceinline__ int perm8(int i) { return (i < 4) ? 2 * i : 2 * (i - 4) + 1; }

__device__ __forceinline__ float totf32(float x) {
    uint32_t r;
    asm("cvt.rna.tf32.f32 %0, %1;" : "=r"(r) : "f"(x));
    return __uint_as_float(r);
}

__device__ __forceinline__ void mma_tf32(float& c0, float& c1, float& c2, float& c3,
    float a0, float a1, float a2, float a3, float b0, float b1) {
    asm volatile(
        "mma.sync.aligned.m16n8k8.row.col.f32.tf32.tf32.f32 "
        "{%0,%1,%2,%3}, {%4,%5,%6,%7}, {%8,%9}, {%0,%1,%2,%3};"
        : "+f"(c0), "+f"(c1), "+f"(c2), "+f"(c3)
        : "r"(__float_as_uint(a0)), "r"(__float_as_uint(a1)),
          "r"(__float_as_uint(a2)), "r"(__float_as_uint(a3)),
          "r"(__float_as_uint(b0)), "r"(__float_as_uint(b1)));
}

#define CP_ASYNC16(dst, src) \
    asm volatile("cp.async.cg.shared.global [%0], [%1], 16;" :: "r"(dst), "l"(src))
#define CP_COMMIT()  asm volatile("cp.async.commit_group;" ::: "memory")
#define CP_WAIT0()   asm volatile("cp.async.wait_group 0;" ::: "memory")

__device__ __forceinline__ uint32_t smem_to_u32(const void* p) {
    uint32_t a;
    asm("{ .reg .u64 t; cvta.to.shared.u64 t, %1; cvt.u32.u64 %0, t; }"
        : "=r"(a) : "l"(p));
    return a;
}

__device__ __forceinline__ float ex2(float x) {
    float y;
    asm("ex2.approx.f32 %0, %1;" : "=f"(y) : "f"(x));
    return y;
}

// ===========================================================================
// prep: W -> tf32-rounded, k pair-permuted  (x prep is fused into proj)
// ===========================================================================
__global__ __launch_bounds__(256) void wprep_kernel(
    const float* __restrict__ Wk,
    const float* __restrict__ Wq,
    const float* __restrict__ Wv)
{
    int idx = blockIdx.x * 256 + threadIdx.x;
    if (idx >= 3 * HDIM * EMB) return;
    int which = idx >> 17;
    int within = idx & ((HDIM * EMB) - 1);
    int k = within & (EMB - 1);
    int n = within >> 10;
    const float* W = (which == 0) ? Wk : (which == 1) ? Wq : Wv;
    g_Wp[which * HDIM * EMB + n * EMB + (k & ~7) + perm8(k & 7)] = totf32(W[within]);
}

// ===========================================================================
// Projection GEMM, tf32 single-product, x converted+permuted in-kernel.
// grid (128 m-tiles, 3 heads), 256 threads (8 warps x 16 rows).
// smem tiles: x [128][64], W [128][64], row stride 288 B (conflict-free LDS.64)
// ===========================================================================
#define PJ_RS   288
#define PJ_X    0
#define PJ_W    36864
#define PJ_SMEM 73728

extern __shared__ char dsmem[];

__global__ __launch_bounds__(256) void proj_mma_kernel(const float* __restrict__ x)
{
    char* smem = dsmem;
    const int tid  = threadIdx.x;
    const int lane = tid & 31;
    const int w    = tid >> 5;
    const int m0   = blockIdx.x * 128;
    const int which = blockIdx.y;

    float o[16][4];
#pragma unroll
    for (int t = 0; t < 16; t++)
#pragma unroll
        for (int k = 0; k < 4; k++) o[t][k] = 0.0f;

    const uint32_t a_row0 = (uint32_t)(w * 16 + (lane >> 2)) * PJ_RS + (lane & 3) * 8;
    const uint32_t b_base = (uint32_t)(lane >> 2) * PJ_RS + (lane & 3) * 8;

    for (int e0 = 0; e0 < EMB; e0 += 64) {
        __syncthreads();
        // ---- x tile: load raw fp32, cvt to tf32 + pair-permute in regs ----
        // dest group order = [s0,s4,s1,s5, s2,s6,s3,s7]
#pragma unroll
        for (int j = 0; j < 4; j++) {
            int idx = tid + j * 256;               // 0..1023
            int row = idx >> 3, c8 = idx & 7;      // 128 rows x 8 groups of 8
            const float* src = x + (size_t)(m0 + row) * EMB + e0 + c8 * 8;
            float4 u = *(const float4*)(src);
            float4 v = *(const float4*)(src + 4);
            float s0 = totf32(u.x), s1 = totf32(u.y), s2 = totf32(u.z), s3 = totf32(u.w);
            float s4 = totf32(v.x), s5 = totf32(v.y), s6 = totf32(v.z), s7 = totf32(v.w);
            float* dst = (float*)(smem + PJ_X + row * PJ_RS + c8 * 32);
            *(float4*)(dst)     = make_float4(s0, s4, s1, s5);
            *(float4*)(dst + 4) = make_float4(s2, s6, s3, s7);
        }
        // ---- W tile: straight uint4 copies (perm pre-applied in gmem) ----
#pragma unroll
        for (int j = 0; j < 8; j++) {
            int idx = tid + j * 256;               // 0..2047
            int row = idx >> 4, c16 = idx & 15;
            *(uint4*)(smem + PJ_W + row * PJ_RS + c16 * 16) =
                *(const uint4*)(g_Wp + (size_t)(which * HDIM + row) * EMB + e0 + c16 * 4);
        }
        __syncthreads();

#pragma unroll
        for (int st = 0; st < 8; st++) {
            float2 aA = *(const float2*)(smem + PJ_X + a_row0 + st * 32);
            float2 aB = *(const float2*)(smem + PJ_X + a_row0 + 8 * PJ_RS + st * 32);
#pragma unroll
            for (int nt = 0; nt < 16; nt++) {
                float2 b = *(const float2*)(smem + PJ_W + b_base
                                            + (uint32_t)(nt * 8) * PJ_RS + st * 32);
                mma_tf32(o[nt][0], o[nt][1], o[nt][2], o[nt][3],
                         aA.x, aB.x, aA.y, aB.y, b.x, b.y);
            }
        }
    }

    // ---- epilogue ----
    const int r0 = m0 + w * 16 + (lane >> 2);
    const int r1 = r0 + 8;
    if (which == 2) {
        // V: transpose into g_Vt[b][dim][seq], keys pair-permuted
        const int b0i = r0 >> 12, s0 = r0 & 4095;
        const int b1i = r1 >> 12, s1 = r1 & 4095;
        const int sp0 = (s0 & ~7) + perm8(s0 & 7);
        const int sp1 = (s1 & ~7) + perm8(s1 & 7);
#pragma unroll
        for (int nt = 0; nt < 16; nt++) {
            int col = nt * 8 + 2 * (lane & 3);
            g_Vt[((size_t)b0i * HDIM + col)     * SEQ + sp0] = totf32(o[nt][0]);
            g_Vt[((size_t)b0i * HDIM + col + 1) * SEQ + sp0] = totf32(o[nt][1]);
            g_Vt[((size_t)b1i * HDIM + col)     * SEQ + sp1] = totf32(o[nt][2]);
            g_Vt[((size_t)b1i * HDIM + col + 1) * SEQ + sp1] = totf32(o[nt][3]);
        }
    } else {
        // Q (scaled, base-2 softmax) / K: dims pair-permuted
        const float scale = (which == 1) ? (0.03125f * 1.44269504f) : 1.0f;
        float* dst = (which == 1) ? g_Q : g_K;
#pragma unroll
        for (int nt = 0; nt < 16; nt++) {
            int col = nt * 8 + 2 * (lane & 3);
            int p0 = (col & ~7) + perm8(col & 7);
            int p1 = (col & ~7) + perm8((col & 7) + 1);
            dst[(size_t)r0 * HDIM + p0] = totf32(o[nt][0] * scale);
            dst[(size_t)r0 * HDIM + p1] = totf32(o[nt][1] * scale);
            dst[(size_t)r1 * HDIM + p0] = totf32(o[nt][2] * scale);
            dst[(size_t)r1 * HDIM + p1] = totf32(o[nt][3] * scale);
        }
    }
}

// ===========================================================================
// Flash attention, tf32 single-product, 8 warps, FA2 key-split halves.
// ONE q-tile per CTA, scheduled longest-first: grid (64, 4), qt = 63 - bx.
// K tile [64 keys][128 dims] RS=544; V^T tile [128 dims][64 keys] RS=288.
// Double-buffered: 2*(34816+36864) = 143360 B, 1 CTA/SM.
// ===========================================================================
#define AK_RS  544
#define AV_RS  288
#define A_K    0
#define A_V    34816
#define A_BUF  71680
#define A_SMEM 143360
#define M_INIT (-1e30f)

__device__ __forceinline__ void prefetch_kv(uint32_t sb_buf, int b, int grow, int kt, int tid)
{
#pragma unroll
    for (int j = 0; j < 8; j++) {
        int idx = tid + j * 256;                 // 0..2047
        int row = idx >> 5, c = idx & 31;        // K: 64 rows x 32 uint4
        CP_ASYNC16(sb_buf + A_K + (uint32_t)row * AK_RS + c * 16,
                   (const void*)(g_K + (size_t)(grow + row) * HDIM + c * 4));
    }
#pragma unroll
    for (int j = 0; j < 8; j++) {
        int idx = tid + j * 256;
        int row = idx >> 4, c = idx & 15;        // V^T: 128 rows x 16 uint4
        CP_ASYNC16(sb_buf + A_V + (uint32_t)row * AV_RS + c * 16,
                   (const void*)(g_Vt + ((size_t)b * HDIM + row) * SEQ + kt * 64 + c * 4));
    }
    CP_COMMIT();
}

__global__ __launch_bounds__(256, 1) void attn_mma_kernel(float* __restrict__ out)
{
    char* smem = dsmem;
    uint32_t sb = smem_to_u32(smem);
    const int tid  = threadIdx.x;
    const int lane = tid & 31;
    const int w    = tid >> 5;
    const int wq   = w & 3;           // query-row group (16 rows)
    const int nh   = w >> 2;          // key half: 0 -> [0:32), 1 -> [32:64)
    const int b    = blockIdx.y;
    const int qt   = 63 - blockIdx.x; // longest-first scheduling
    const int nkt  = qt + 1;
    const int bbase = b * SEQ;

    const int r0 = wq * 16 + (lane >> 2);        // tile-local row (0..63)
    // P-shuffle lane map (C-frag -> A-frag)
    const int pc = lane & 3;
    const int src_lo = (lane & 28) | (pc >> 1);
    const int src_hi = src_lo | 2;
    const int pe = pc & 1;

    // ---- hoist Q fragments (tf32, dims pair-permuted in gmem) ----
    float qf[16][4];
    {
        const float* q0 = g_Q + (size_t)(bbase + qt * 64 + wq * 16 + (lane >> 2)) * HDIM
                          + (lane & 3) * 2;
#pragma unroll
        for (int st = 0; st < 16; st++) {
            float2 u = *(const float2*)(q0 + st * 8);
            float2 v = *(const float2*)(q0 + 8 * HDIM + st * 8);
            qf[st][0] = u.x; qf[st][1] = v.x; qf[st][2] = u.y; qf[st][3] = v.y;
        }
    }

    float o[16][4];
#pragma unroll
    for (int t = 0; t < 16; t++)
#pragma unroll
        for (int k = 0; k < 4; k++) o[t][k] = 0.0f;
    float m0 = M_INIT, m1 = M_INIT, l0 = 0.0f, l1 = 0.0f;

    prefetch_kv(sb, b, bbase, 0, tid);       // kt=0 -> buf 0

    for (int kt = 0; kt < nkt; kt++) {
        CP_WAIT0();
        __syncthreads();
        if (kt + 1 < nkt)
            prefetch_kv(sb + ((kt + 1) & 1) * A_BUF, b,
                        bbase + (kt + 1) * 64, kt + 1, tid);
        const uint32_t kb = sb + (kt & 1) * A_BUF;

        // ---- S = Q K^T on this warp's 32-key half ----
        float s[4][4];
#pragma unroll
        for (int t = 0; t < 4; t++)
#pragma unroll
            for (int k = 0; k < 4; k++) s[t][k] = 0.0f;

        const uint32_t kfb = kb + A_K + (uint32_t)(nh * 32 + (lane >> 2)) * AK_RS
                           + (lane & 3) * 8;
#pragma unroll
        for (int st = 0; st < 16; st++) {
#pragma unroll
            for (int np = 0; np < 4; np++) {
                float2 bb = *(const float2*)(smem + (kfb - sb)
                             + (uint32_t)(np * 8) * AK_RS + st * 32);
                mma_tf32(s[np][0], s[np][1], s[np][2], s[np][3],
                         qf[st][0], qf[st][1], qf[st][2], qf[st][3], bb.x, bb.y);
            }
        }

        // ---- causal mask on diagonal tile ----
        if (kt == qt) {
            const int rr0 = r0, rr1 = r0 + 8;
#pragma unroll
            for (int nt = 0; nt < 4; nt++) {
                int c = nh * 32 + nt * 8 + 2 * (lane & 3);
                if (c     > rr0) s[nt][0] = -INFINITY;
                if (c + 1 > rr0) s[nt][1] = -INFINITY;
                if (c     > rr1) s[nt][2] = -INFINITY;
                if (c + 1 > rr1) s[nt][3] = -INFINITY;
            }
        }

        // ---- online softmax (base-2, independent per key-half) ----
        float rmax0 = -INFINITY, rmax1 = -INFINITY;
#pragma unroll
        for (int nt = 0; nt < 4; nt++) {
            rmax0 = fmaxf(rmax0, fmaxf(s[nt][0], s[nt][1]));
            rmax1 = fmaxf(rmax1, fmaxf(s[nt][2], s[nt][3]));
        }
        rmax0 = fmaxf(rmax0, __shfl_xor_sync(FULLM, rmax0, 1));
        rmax0 = fmaxf(rmax0, __shfl_xor_sync(FULLM, rmax0, 2));
        rmax1 = fmaxf(rmax1, __shfl_xor_sync(FULLM, rmax1, 1));
        rmax1 = fmaxf(rmax1, __shfl_xor_sync(FULLM, rmax1, 2));

        float mn0 = fmaxf(m0, rmax0), mn1 = fmaxf(m1, rmax1);
        float alpha0 = ex2(m0 - mn0), alpha1 = ex2(m1 - mn1);
        m0 = mn0; m1 = mn1;

        float sum0 = 0.0f, sum1 = 0.0f;
#pragma unroll
        for (int nt = 0; nt < 4; nt++) {
            s[nt][0] = ex2(s[nt][0] - mn0);
            s[nt][1] = ex2(s[nt][1] - mn0);
            s[nt][2] = ex2(s[nt][2] - mn1);
            s[nt][3] = ex2(s[nt][3] - mn1);
            sum0 += s[nt][0] + s[nt][1];
            sum1 += s[nt][2] + s[nt][3];
        }
        sum0 += __shfl_xor_sync(FULLM, sum0, 1);
        sum0 += __shfl_xor_sync(FULLM, sum0, 2);
        sum1 += __shfl_xor_sync(FULLM, sum1, 1);
        sum1 += __shfl_xor_sync(FULLM, sum1, 2);
        l0 = l0 * alpha0 + sum0;
        l1 = l1 * alpha1 + sum1;

#pragma unroll
        for (int t = 0; t < 16; t++) {
            o[t][0] *= alpha0; o[t][1] *= alpha0;
            o[t][2] *= alpha1; o[t][3] *= alpha1;
        }

        // ---- O += P V over this warp's 32-key range ----
        const uint32_t vfb = (kb - sb) + A_V + (uint32_t)(lane >> 2) * AV_RS
                           + (nh * 32) * 4 + (lane & 3) * 8;
#pragma unroll
        for (int t = 0; t < 4; t++) {
            // C-frag -> A-frag remap of P via shuffles
            float v0 = __shfl_sync(FULLM, s[t][0], src_lo);
            float v1 = __shfl_sync(FULLM, s[t][1], src_lo);
            float v2 = __shfl_sync(FULLM, s[t][2], src_lo);
            float v3 = __shfl_sync(FULLM, s[t][3], src_lo);
            float h0 = __shfl_sync(FULLM, s[t][0], src_hi);
            float h1 = __shfl_sync(FULLM, s[t][1], src_hi);
            float h2 = __shfl_sync(FULLM, s[t][2], src_hi);
            float h3 = __shfl_sync(FULLM, s[t][3], src_hi);
            float pa0 = totf32(pe ? v1 : v0);
            float pa1 = totf32(pe ? v3 : v2);
            float pa2 = totf32(pe ? h1 : h0);
            float pa3 = totf32(pe ? h3 : h2);
#pragma unroll
            for (int nd = 0; nd < 16; nd++) {
                float2 bb = *(const float2*)(smem + vfb
                             + (uint32_t)(nd * 8) * AV_RS + t * 32);
                mma_tf32(o[nd][0], o[nd][1], o[nd][2], o[nd][3],
                         pa0, pa1, pa2, pa3, bb.x, bb.y);
            }
        }
    }

    // ---- merge the two key-halves' (O, m, l), normalize, store ----
    __syncthreads();   // all smem reads done; reuse buf0 as scratch
    float* O1s = (float*)(smem);                // [64][128]
    float* M1s = (float*)(smem + 32768);        // [64]
    float* L1s = M1s + 64;                      // [64]
    if (nh == 1) {
#pragma unroll
        for (int nt = 0; nt < 16; nt++) {
            int col = nt * 8 + 2 * (lane & 3);
            *(float2*)(O1s + (r0)     * 128 + col) = make_float2(o[nt][0], o[nt][1]);
            *(float2*)(O1s + (r0 + 8) * 128 + col) = make_float2(o[nt][2], o[nt][3]);
        }
        if ((lane & 3) == 0) {
            M1s[r0] = m0;  M1s[r0 + 8] = m1;
            L1s[r0] = l0;  L1s[r0 + 8] = l1;
        }
    }
    __syncthreads();
    if (nh == 0) {
        float m1a = M1s[r0],     l1a = L1s[r0];
        float m1b = M1s[r0 + 8], l1b = L1s[r0 + 8];
        float Ma = fmaxf(m0, m1a), Mb = fmaxf(m1, m1b);
        float b0a = ex2(m0 - Ma),  b1a = ex2(m1a - Ma);
        float b0b = ex2(m1 - Mb),  b1b = ex2(m1b - Mb);
        float invLa = 1.0f / (l0 * b0a + l1a * b1a);
        float invLb = 1.0f / (l1 * b0b + l1b * b1b);
        const int gr0 = bbase + qt * 64 + r0;
        const int gr1 = gr0 + 8;
#pragma unroll
        for (int nt = 0; nt < 16; nt++) {
            int col = nt * 8 + 2 * (lane & 3);
            float2 p0 = *(const float2*)(O1s + (r0)     * 128 + col);
            float2 p1 = *(const float2*)(O1s + (r0 + 8) * 128 + col);
            *(float2*)(out + (size_t)gr0 * HDIM + col) = make_float2(
                (o[nt][0] * b0a + p0.x * b1a) * invLa,
                (o[nt][1] * b0a + p0.y * b1a) * invLa);
            *(float2*)(out + (size_t)gr1 * HDIM + col) = make_float2(
                (o[nt][2] * b0b + p1.x * b1b) * invLb,
                (o[nt][3] * b0b + p1.y * b1b) * invLb);
        }
    }
}

// ---------------------------------------------------------------------------
extern "C" void kernel_launch(void* const* d_in, const int* in_sizes, int n_in,
                              void* d_out, int out_size)
{
    const float* x  = (const float*)d_in[0];
    const float* Wk = (const float*)d_in[1];
    const float* Wq = (const float*)d_in[2];
    const float* Wv = (const float*)d_in[3];
    float* out = (float*)d_out;

    static bool attr_set = false;
    if (!attr_set) {
        cudaFuncSetAttribute(proj_mma_kernel,
                             cudaFuncAttributeMaxDynamicSharedMemorySize, PJ_SMEM);
        cudaFuncSetAttribute(attn_mma_kernel,
                             cudaFuncAttributeMaxDynamicSharedMemorySize, A_SMEM);
        attr_set = true;
    }

    // 1) prep W -> tf32-rounded, pair-permuted (x prep fused into proj)
    wprep_kernel<<<(3 * HDIM * EMB + 255) / 256, 256>>>(Wk, Wq, Wv);

    // 2) Q/K/V projections, tf32 single-product tensor-core GEMM
    proj_mma_kernel<<<dim3(128, 3), 256, PJ_SMEM>>>(x);

    // 3) causal flash attention, tf32, one q-tile per CTA, longest-first
    attn_mma_kernel<<<dim3(64, BATCH), 256, A_SMEM>>>(out);
}

// round 13
// speedup vs baseline: 1.1898x; 1.0252x over previous
#include <cuda_runtime.h>
#include <math.h>
#include <cstdint>

#define BATCH 4
#define SEQ   4096
#define EMB   1024
#define HDIM  128
#define FULLM 0xffffffffu

// ---------------------------------------------------------------------------
// scratch (allocation-free: __device__ globals) — all tf32-rounded fp32
// ---------------------------------------------------------------------------
// Q, K: [b*SEQ+row][dim], dims pair-permuted within 8-groups ((c,c+4) adjacent)
__device__ float g_Q[(size_t)BATCH * SEQ * HDIM];
__device__ float g_K[(size_t)BATCH * SEQ * HDIM];
// V transposed: [b][dim][seq], keys pair-permuted within 8-groups
__device__ float g_Vt[(size_t)BATCH * HDIM * SEQ];
// W: [which][n][k], k pair-permuted; which: 0=K,1=Q,2=V
__device__ float g_Wp[3 * HDIM * EMB];
// split-K attention partials (numerator O, running max m, running sum l)
__device__ float g_O0[(size_t)BATCH * SEQ * HDIM];
__device__ float g_O1[(size_t)BATCH * SEQ * HDIM];
__device__ float g_Mp[2][BATCH * SEQ];
__device__ float g_Lp[2][BATCH * SEQ];

// ===========================================================================
// helpers
// ===========================================================================
__device__ __forceinline__ int perm8(int i) { return (i < 4) ? 2 * i : 2 * (i - 4) + 1; }

__device__ __forceinline__ float totf32(float x) {
    uint32_t r;
    asm("cvt.rna.tf32.f32 %0, %1;" : "=r"(r) : "f"(x));
    return __uint_as_float(r);
}

__device__ __forceinline__ void mma_tf32(float& c0, float& c1, float& c2, float& c3,
    float a0, float a1, float a2, float a3, float b0, float b1) {
    asm volatile(
        "mma.sync.aligned.m16n8k8.row.col.f32.tf32.tf32.f32 "
        "{%0,%1,%2,%3}, {%4,%5,%6,%7}, {%8,%9}, {%0,%1,%2,%3};"
        : "+f"(c0), "+f"(c1), "+f"(c2), "+f"(c3)
        : "r"(__float_as_uint(a0)), "r"(__float_as_uint(a1)),
          "r"(__float_as_uint(a2)), "r"(__float_as_uint(a3)),
          "r"(__float_as_uint(b0)), "r"(__float_as_uint(b1)));
}

#define CP_ASYNC16(dst, src) \
    asm volatile("cp.async.cg.shared.global [%0], [%1], 16;" :: "r"(dst), "l"(src))
#define CP_COMMIT()  asm volatile("cp.async.commit_group;" ::: "memory")
#define CP_WAIT0()   asm volatile("cp.async.wait_group 0;" ::: "memory")

__device__ __forceinline__ uint32_t smem_to_u32(const void* p) {
    uint32_t a;
    asm("{ .reg .u64 t; cvta.to.shared.u64 t, %1; cvt.u32.u64 %0, t; }"
        : "=r"(a) : "l"(p));
    return a;
}

__device__ __forceinline__ float ex2(float x) {
    float y;
    asm("ex2.approx.f32 %0, %1;" : "=f"(y) : "f"(x));
    return y;
}

// ===========================================================================
// prep: W -> tf32-rounded, k pair-permuted  (x prep is fused into proj)
// ===========================================================================
__global__ __launch_bounds__(256) void wprep_kernel(
    const float* __restrict__ Wk,
    const float* __restrict__ Wq,
    const float* __restrict__ Wv)
{
    int idx = blockIdx.x * 256 + threadIdx.x;
    if (idx >= 3 * HDIM * EMB) return;
    int which = idx >> 17;
    int within = idx & ((HDIM * EMB) - 1);
    int k = within & (EMB - 1);
    int n = within >> 10;
    const float* W = (which == 0) ? Wk : (which == 1) ? Wq : Wv;
    g_Wp[which * HDIM * EMB + n * EMB + (k & ~7) + perm8(k & 7)] = totf32(W[within]);
}

// ===========================================================================
// Projection GEMM, tf32 single-product, x converted+permuted in-kernel.
// grid (128 m-tiles, 3 heads), 256 threads (8 warps x 16 rows). 3 CTAs/SM.
// ===========================================================================
#define PJ_RS   288
#define PJ_X    0
#define PJ_W    36864
#define PJ_SMEM 73728

extern __shared__ char dsmem[];

__global__ __launch_bounds__(256) void proj_mma_kernel(const float* __restrict__ x)
{
    char* smem = dsmem;
    const int tid  = threadIdx.x;
    const int lane = tid & 31;
    const int w    = tid >> 5;
    const int m0   = blockIdx.x * 128;
    const int which = blockIdx.y;

    float o[16][4];
#pragma unroll
    for (int t = 0; t < 16; t++)
#pragma unroll
        for (int k = 0; k < 4; k++) o[t][k] = 0.0f;

    const uint32_t a_row0 = (uint32_t)(w * 16 + (lane >> 2)) * PJ_RS + (lane & 3) * 8;
    const uint32_t b_base = (uint32_t)(lane >> 2) * PJ_RS + (lane & 3) * 8;

    for (int e0 = 0; e0 < EMB; e0 += 64) {
        __syncthreads();
        // ---- x tile: load raw fp32, cvt to tf32 + pair-permute in regs ----
#pragma unroll
        for (int j = 0; j < 4; j++) {
            int idx = tid + j * 256;
            int row = idx >> 3, c8 = idx & 7;
            const float* src = x + (size_t)(m0 + row) * EMB + e0 + c8 * 8;
            float4 u = *(const float4*)(src);
            float4 v = *(const float4*)(src + 4);
            float s0 = totf32(u.x), s1 = totf32(u.y), s2 = totf32(u.z), s3 = totf32(u.w);
            float s4 = totf32(v.x), s5 = totf32(v.y), s6 = totf32(v.z), s7 = totf32(v.w);
            float* dst = (float*)(smem + PJ_X + row * PJ_RS + c8 * 32);
            *(float4*)(dst)     = make_float4(s0, s4, s1, s5);
            *(float4*)(dst + 4) = make_float4(s2, s6, s3, s7);
        }
        // ---- W tile: straight uint4 copies (perm pre-applied in gmem) ----
#pragma unroll
        for (int j = 0; j < 8; j++) {
            int idx = tid + j * 256;
            int row = idx >> 4, c16 = idx & 15;
            *(uint4*)(smem + PJ_W + row * PJ_RS + c16 * 16) =
                *(const uint4*)(g_Wp + (size_t)(which * HDIM + row) * EMB + e0 + c16 * 4);
        }
        __syncthreads();

#pragma unroll
        for (int st = 0; st < 8; st++) {
            float2 aA = *(const float2*)(smem + PJ_X + a_row0 + st * 32);
            float2 aB = *(const float2*)(smem + PJ_X + a_row0 + 8 * PJ_RS + st * 32);
#pragma unroll
            for (int nt = 0; nt < 16; nt++) {
                float2 b = *(const float2*)(smem + PJ_W + b_base
                                            + (uint32_t)(nt * 8) * PJ_RS + st * 32);
                mma_tf32(o[nt][0], o[nt][1], o[nt][2], o[nt][3],
                         aA.x, aB.x, aA.y, aB.y, b.x, b.y);
            }
        }
    }

    // ---- epilogue ----
    const int r0 = m0 + w * 16 + (lane >> 2);
    const int r1 = r0 + 8;
    if (which == 2) {
        const int b0i = r0 >> 12, s0 = r0 & 4095;
        const int b1i = r1 >> 12, s1 = r1 & 4095;
        const int sp0 = (s0 & ~7) + perm8(s0 & 7);
        const int sp1 = (s1 & ~7) + perm8(s1 & 7);
#pragma unroll
        for (int nt = 0; nt < 16; nt++) {
            int col = nt * 8 + 2 * (lane & 3);
            g_Vt[((size_t)b0i * HDIM + col)     * SEQ + sp0] = totf32(o[nt][0]);
            g_Vt[((size_t)b0i * HDIM + col + 1) * SEQ + sp0] = totf32(o[nt][1]);
            g_Vt[((size_t)b1i * HDIM + col)     * SEQ + sp1] = totf32(o[nt][2]);
            g_Vt[((size_t)b1i * HDIM + col + 1) * SEQ + sp1] = totf32(o[nt][3]);
        }
    } else {
        const float scale = (which == 1) ? (0.03125f * 1.44269504f) : 1.0f;
        float* dst = (which == 1) ? g_Q : g_K;
#pragma unroll
        for (int nt = 0; nt < 16; nt++) {
            int col = nt * 8 + 2 * (lane & 3);
            int p0 = (col & ~7) + perm8(col & 7);
            int p1 = (col & ~7) + perm8((col & 7) + 1);
            dst[(size_t)r0 * HDIM + p0] = totf32(o[nt][0] * scale);
            dst[(size_t)r0 * HDIM + p1] = totf32(o[nt][1] * scale);
            dst[(size_t)r1 * HDIM + p0] = totf32(o[nt][2] * scale);
            dst[(size_t)r1 * HDIM + p1] = totf32(o[nt][3] * scale);
        }
    }
}

// ===========================================================================
// Flash attention, tf32, 8 warps, FA2 key-split halves IN-CTA + 2-way
// key-parity split ACROSS CTAs (kt ≡ rho mod 2), partials to gmem.
// Pair trick: CTA handles q-tiles p and 63-p -> ~32.5 iters/CTA.
// grid (64, 4): p = bx>>1, rho = bx&1. 256 CTAs, 2 CTAs/SM (106496 B, <=128r).
// Q in smem (no reg hoist), K/V single-buffered (co-CTA hides load latency).
// ===========================================================================
#define AQ_RS  544
#define AK_RS  544
#define AV_RS  288
#define A_Q    0
#define A_K    34816
#define A_V    69632
#define A_SMEM 106496
#define M_INIT (-1e30f)

__global__ __launch_bounds__(256, 2) void attn_mma_kernel()
{
    char* smem = dsmem;
    uint32_t sb = smem_to_u32(smem);
    const int tid  = threadIdx.x;
    const int lane = tid & 31;
    const int w    = tid >> 5;
    const int wq   = w & 3;           // query-row group (16 rows)
    const int nh   = w >> 2;          // key half: 0 -> [0:32), 1 -> [32:64)
    const int b    = blockIdx.y;
    const int pair = blockIdx.x >> 1;
    const int rho  = blockIdx.x & 1;  // key-tile parity
    const int bbase = b * SEQ;

    const int r0 = wq * 16 + (lane >> 2);        // tile-local row (0..63)
    // P-shuffle lane map (C-frag -> A-frag)
    const int pc = lane & 3;
    const int src_lo = (lane & 28) | (pc >> 1);
    const int src_hi = src_lo | 2;
    const int pe = pc & 1;

    // fragment addressing (byte offsets within smem)
    const uint32_t qfo = (uint32_t)(wq * 16 + (lane >> 2)) * AQ_RS + (lane & 3) * 8;
    const uint32_t kfo = A_K + (uint32_t)(nh * 32 + (lane >> 2)) * AK_RS + (lane & 3) * 8;
    const uint32_t vfo = A_V + (uint32_t)(lane >> 2) * AV_RS + (nh * 32) * 4 + (lane & 3) * 8;

    for (int half = 0; half < 2; half++) {
        const int qt = half ? (63 - pair) : pair;

        // ---- stage Q tile into smem (already tf32 + pair-permuted) ----
        __syncthreads();
#pragma unroll
        for (int j = 0; j < 8; j++) {
            int idx = tid + j * 256;               // 0..2047
            int row = idx >> 5, c = idx & 31;
            *(uint4*)(smem + A_Q + (uint32_t)row * AQ_RS + c * 16) =
                *(const uint4*)(g_Q + (size_t)(bbase + qt * 64 + row) * HDIM + c * 4);
        }
        __syncthreads();

        float o[16][4];
#pragma unroll
        for (int t = 0; t < 16; t++)
#pragma unroll
            for (int k = 0; k < 4; k++) o[t][k] = 0.0f;
        float m0 = M_INIT, m1 = M_INIT, l0 = 0.0f, l1 = 0.0f;

        for (int kt = rho; kt <= qt; kt += 2) {
            const int grow = bbase + kt * 64;

            // ---- K and V^T loads (single buffer; trailing barrier freed it) ----
#pragma unroll
            for (int j = 0; j < 8; j++) {
                int idx = tid + j * 256;
                int row = idx >> 5, c = idx & 31;
                CP_ASYNC16(sb + A_K + (uint32_t)row * AK_RS + c * 16,
                           (const void*)(g_K + (size_t)(grow + row) * HDIM + c * 4));
            }
#pragma unroll
            for (int j = 0; j < 8; j++) {
                int idx = tid + j * 256;
                int row = idx >> 4, c = idx & 15;
                CP_ASYNC16(sb + A_V + (uint32_t)row * AV_RS + c * 16,
                           (const void*)(g_Vt + ((size_t)b * HDIM + row) * SEQ
                                         + kt * 64 + c * 4));
            }
            CP_COMMIT();
            CP_WAIT0();
            __syncthreads();

            // ---- S = Q K^T on this warp's 32-key half ----
            float s[4][4];
#pragma unroll
            for (int t = 0; t < 4; t++)
#pragma unroll
                for (int k = 0; k < 4; k++) s[t][k] = 0.0f;

#pragma unroll
            for (int st = 0; st < 16; st++) {
                float2 aA = *(const float2*)(smem + A_Q + qfo + st * 32);
                float2 aB = *(const float2*)(smem + A_Q + qfo + 8 * AQ_RS + st * 32);
#pragma unroll
                for (int np = 0; np < 4; np++) {
                    float2 bb = *(const float2*)(smem + kfo
                                 + (uint32_t)(np * 8) * AK_RS + st * 32);
                    mma_tf32(s[np][0], s[np][1], s[np][2], s[np][3],
                             aA.x, aB.x, aA.y, aB.y, bb.x, bb.y);
                }
            }

            // ---- causal mask on diagonal tile ----
            if (kt == qt) {
                const int rr0 = r0, rr1 = r0 + 8;
#pragma unroll
                for (int nt = 0; nt < 4; nt++) {
                    int c = nh * 32 + nt * 8 + 2 * (lane & 3);
                    if (c     > rr0) s[nt][0] = -INFINITY;
                    if (c + 1 > rr0) s[nt][1] = -INFINITY;
                    if (c     > rr1) s[nt][2] = -INFINITY;
                    if (c + 1 > rr1) s[nt][3] = -INFINITY;
                }
            }

            // ---- online softmax (base-2, independent per key-half) ----
            float rmax0 = -INFINITY, rmax1 = -INFINITY;
#pragma unroll
            for (int nt = 0; nt < 4; nt++) {
                rmax0 = fmaxf(rmax0, fmaxf(s[nt][0], s[nt][1]));
                rmax1 = fmaxf(rmax1, fmaxf(s[nt][2], s[nt][3]));
            }
            rmax0 = fmaxf(rmax0, __shfl_xor_sync(FULLM, rmax0, 1));
            rmax0 = fmaxf(rmax0, __shfl_xor_sync(FULLM, rmax0, 2));
            rmax1 = fmaxf(rmax1, __shfl_xor_sync(FULLM, rmax1, 1));
            rmax1 = fmaxf(rmax1, __shfl_xor_sync(FULLM, rmax1, 2));

            float mn0 = fmaxf(m0, rmax0), mn1 = fmaxf(m1, rmax1);
            float alpha0 = ex2(m0 - mn0), alpha1 = ex2(m1 - mn1);
            m0 = mn0; m1 = mn1;

            float sum0 = 0.0f, sum1 = 0.0f;
#pragma unroll
            for (int nt = 0; nt < 4; nt++) {
                s[nt][0] = ex2(s[nt][0] - mn0);
                s[nt][1] = ex2(s[nt][1] - mn0);
                s[nt][2] = ex2(s[nt][2] - mn1);
                s[nt][3] = ex2(s[nt][3] - mn1);
                sum0 += s[nt][0] + s[nt][1];
                sum1 += s[nt][2] + s[nt][3];
            }
            sum0 += __shfl_xor_sync(FULLM, sum0, 1);
            sum0 += __shfl_xor_sync(FULLM, sum0, 2);
            sum1 += __shfl_xor_sync(FULLM, sum1, 1);
            sum1 += __shfl_xor_sync(FULLM, sum1, 2);
            l0 = l0 * alpha0 + sum0;
            l1 = l1 * alpha1 + sum1;

#pragma unroll
            for (int t = 0; t < 16; t++) {
                o[t][0] *= alpha0; o[t][1] *= alpha0;
                o[t][2] *= alpha1; o[t][3] *= alpha1;
            }

            // ---- O += P V over this warp's 32-key range ----
#pragma unroll
            for (int t = 0; t < 4; t++) {
                float v0 = __shfl_sync(FULLM, s[t][0], src_lo);
                float v1 = __shfl_sync(FULLM, s[t][1], src_lo);
                float v2 = __shfl_sync(FULLM, s[t][2], src_lo);
                float v3 = __shfl_sync(FULLM, s[t][3], src_lo);
                float h0 = __shfl_sync(FULLM, s[t][0], src_hi);
                float h1 = __shfl_sync(FULLM, s[t][1], src_hi);
                float h2 = __shfl_sync(FULLM, s[t][2], src_hi);
                float h3 = __shfl_sync(FULLM, s[t][3], src_hi);
                float pa0 = totf32(pe ? v1 : v0);
                float pa1 = totf32(pe ? v3 : v2);
                float pa2 = totf32(pe ? h1 : h0);
                float pa3 = totf32(pe ? h3 : h2);
#pragma unroll
                for (int nd = 0; nd < 16; nd++) {
                    float2 bb = *(const float2*)(smem + vfo
                                 + (uint32_t)(nd * 8) * AV_RS + t * 32);
                    mma_tf32(o[nd][0], o[nd][1], o[nd][2], o[nd][3],
                             pa0, pa1, pa2, pa3, bb.x, bb.y);
                }
            }

            __syncthreads();   // all smem reads done -> buffer reusable
        }

        // ---- merge key-halves; write UNNORMALIZED partial for this parity ----
        float* O1s = (float*)(smem + A_K);          // [64][128] scratch
        float* M1s = (float*)(smem + A_K + 32768);  // [64]
        float* L1s = M1s + 64;                      // [64]
        if (nh == 1) {
#pragma unroll
            for (int nt = 0; nt < 16; nt++) {
                int col = nt * 8 + 2 * (lane & 3);
                *(float2*)(O1s + (r0)     * 128 + col) = make_float2(o[nt][0], o[nt][1]);
                *(float2*)(O1s + (r0 + 8) * 128 + col) = make_float2(o[nt][2], o[nt][3]);
            }
            if ((lane & 3) == 0) {
                M1s[r0] = m0;  M1s[r0 + 8] = m1;
                L1s[r0] = l0;  L1s[r0 + 8] = l1;
            }
        }
        __syncthreads();
        if (nh == 0) {
            float* Op = rho ? g_O1 : g_O0;
            float m1a = M1s[r0],     l1a = L1s[r0];
            float m1b = M1s[r0 + 8], l1b = L1s[r0 + 8];
            float Ma = fmaxf(m0, m1a), Mb = fmaxf(m1, m1b);
            float b0a = ex2(m0 - Ma),  b1a = ex2(m1a - Ma);
            float b0b = ex2(m1 - Mb),  b1b = ex2(m1b - Mb);
            float La = l0 * b0a + l1a * b1a;
            float Lb = l1 * b0b + l1b * b1b;
            const int gr0 = bbase + qt * 64 + r0;
            const int gr1 = gr0 + 8;
            if ((lane & 3) == 0) {
                g_Mp[rho][gr0] = Ma;  g_Lp[rho][gr0] = La;
                g_Mp[rho][gr1] = Mb;  g_Lp[rho][gr1] = Lb;
            }
#pragma unroll
            for (int nt = 0; nt < 16; nt++) {
                int col = nt * 8 + 2 * (lane & 3);
                float2 p0 = *(const float2*)(O1s + (r0)     * 128 + col);
                float2 p1 = *(const float2*)(O1s + (r0 + 8) * 128 + col);
                *(float2*)(Op + (size_t)gr0 * HDIM + col) = make_float2(
                    o[nt][0] * b0a + p0.x * b1a,
                    o[nt][1] * b0a + p0.y * b1a);
                *(float2*)(Op + (size_t)gr1 * HDIM + col) = make_float2(
                    o[nt][2] * b0b + p1.x * b1b,
                    o[nt][3] * b0b + p1.y * b1b);
            }
        }
    }
}

// ===========================================================================
// Merge the 2 parity partials: out = sum(O_p * 2^(m_p - M)) / sum(l_p * ...)
// ===========================================================================
__global__ __launch_bounds__(128) void attn_merge_kernel(float* __restrict__ out)
{
    const int row = blockIdx.x;          // 0..16383
    const int c   = threadIdx.x;         // 0..127
    float m0 = g_Mp[0][row], m1 = g_Mp[1][row];
    float M  = fmaxf(m0, m1);
    float w0 = ex2(m0 - M), w1 = ex2(m1 - M);
    float L  = g_Lp[0][row] * w0 + g_Lp[1][row] * w1;
    size_t off = (size_t)row * HDIM + c;
    out[off] = (g_O0[off] * w0 + g_O1[off] * w1) / L;
}

// ---------------------------------------------------------------------------
extern "C" void kernel_launch(void* const* d_in, const int* in_sizes, int n_in,
                              void* d_out, int out_size)
{
    const float* x  = (const float*)d_in[0];
    const float* Wk = (const float*)d_in[1];
    const float* Wq = (const float*)d_in[2];
    const float* Wv = (const float*)d_in[3];
    float* out = (float*)d_out;

    static bool attr_set = false;
    if (!attr_set) {
        cudaFuncSetAttribute(proj_mma_kernel,
                             cudaFuncAttributeMaxDynamicSharedMemorySize, PJ_SMEM);
        cudaFuncSetAttribute(attn_mma_kernel,
                             cudaFuncAttributeMaxDynamicSharedMemorySize, A_SMEM);
        attr_set = true;
    }

    // 1) prep W -> tf32-rounded, pair-permuted (x prep fused into proj)
    wprep_kernel<<<(3 * HDIM * EMB + 255) / 256, 256>>>(Wk, Wq, Wv);

    // 2) Q/K/V projections, tf32 single-product tensor-core GEMM
    proj_mma_kernel<<<dim3(128, 3), 256, PJ_SMEM>>>(x);

    // 3) causal flash attention: 256 CTAs (pair x 2 key-parities), 2 CTAs/SM
    attn_mma_kernel<<<dim3(64, BATCH), 256, A_SMEM>>>();

    // 4) merge parity partials
    attn_merge_kernel<<<BATCH * SEQ, 128>>>(out);
}

// round 14
// speedup vs baseline: 1.3270x; 1.1153x over previous
#include <cuda_runtime.h>
#include <math.h>
#include <cstdint>

#define BATCH 4
#define SEQ   4096
#define EMB   1024
#define HDIM  128
#define FULLM 0xffffffffu

// ---------------------------------------------------------------------------
// scratch (allocation-free: __device__ globals) — all tf32-rounded fp32
// ---------------------------------------------------------------------------
// Q, K: [b*SEQ+row][dim], dims pair-permuted within 8-groups ((c,c+4) adjacent)
__device__ float g_Q[(size_t)BATCH * SEQ * HDIM];
__device__ float g_K[(size_t)BATCH * SEQ * HDIM];
// V transposed: [b][dim][seq], keys pair-permuted within 8-groups
__device__ float g_Vt[(size_t)BATCH * HDIM * SEQ];
// W: [which][n][k], k pair-permuted; which: 0=K,1=Q,2=V
__device__ float g_Wp[3 * HDIM * EMB];
// split-K attention partials (numerator O, running max m, running sum l)
__device__ float g_O0[(size_t)BATCH * SEQ * HDIM];
__device__ float g_O1[(size_t)BATCH * SEQ * HDIM];
__device__ float g_Mp[2][BATCH * SEQ];
__device__ float g_Lp[2][BATCH * SEQ];

// ===========================================================================
// helpers
// ===========================================================================
__device__ __forceinline__ int perm8(int i) { return (i < 4) ? 2 * i : 2 * (i - 4) + 1; }

__device__ __forceinline__ float totf32(float x) {
    uint32_t r;
    asm("cvt.rna.tf32.f32 %0, %1;" : "=r"(r) : "f"(x));
    return __uint_as_float(r);
}

__device__ __forceinline__ void mma_tf32(float& c0, float& c1, float& c2, float& c3,
    float a0, float a1, float a2, float a3, float b0, float b1) {
    asm volatile(
        "mma.sync.aligned.m16n8k8.row.col.f32.tf32.tf32.f32 "
        "{%0,%1,%2,%3}, {%4,%5,%6,%7}, {%8,%9}, {%0,%1,%2,%3};"
        : "+f"(c0), "+f"(c1), "+f"(c2), "+f"(c3)
        : "r"(__float_as_uint(a0)), "r"(__float_as_uint(a1)),
          "r"(__float_as_uint(a2)), "r"(__float_as_uint(a3)),
          "r"(__float_as_uint(b0)), "r"(__float_as_uint(b1)));
}

#define CP_ASYNC16(dst, src) \
    asm volatile("cp.async.cg.shared.global [%0], [%1], 16;" :: "r"(dst), "l"(src))
#define CP_COMMIT()  asm volatile("cp.async.commit_group;" ::: "memory")
#define CP_WAIT0()   asm volatile("cp.async.wait_group 0;" ::: "memory")

__device__ __forceinline__ uint32_t smem_to_u32(const void* p) {
    uint32_t a;
    asm("{ .reg .u64 t; cvta.to.shared.u64 t, %1; cvt.u32.u64 %0, t; }"
        : "=r"(a) : "l"(p));
    return a;
}

__device__ __forceinline__ float ex2(float x) {
    float y;
    asm("ex2.approx.f32 %0, %1;" : "=f"(y) : "f"(x));
    return y;
}

// ===========================================================================
// prep: W -> tf32-rounded, k pair-permuted  (x prep is fused into proj)
// ===========================================================================
__global__ __launch_bounds__(256) void wprep_kernel(
    const float* __restrict__ Wk,
    const float* __restrict__ Wq,
    const float* __restrict__ Wv)
{
    int idx = blockIdx.x * 256 + threadIdx.x;
    if (idx >= 3 * HDIM * EMB) return;
    int which = idx >> 17;
    int within = idx & ((HDIM * EMB) - 1);
    int k = within & (EMB - 1);
    int n = within >> 10;
    const float* W = (which == 0) ? Wk : (which == 1) ? Wq : Wv;
    g_Wp[which * HDIM * EMB + n * EMB + (k & ~7) + perm8(k & 7)] = totf32(W[within]);
}

// ===========================================================================
// Projection GEMM, tf32, x converted+permuted in-kernel.
// 2D warp tiling: 8 warps = 4(M) x 2(N); each warp owns 32 rows x 64 cols.
// Halves the redundant B-fragment smem traffic vs M-only split.
// grid (128 m-tiles, 3 heads), 256 threads. 3 CTAs/SM (73728 B).
// ===========================================================================
#define PJ_RS   288
#define PJ_X    0
#define PJ_W    36864
#define PJ_SMEM 73728

extern __shared__ char dsmem[];

__global__ __launch_bounds__(256) void proj_mma_kernel(const float* __restrict__ x)
{
    char* smem = dsmem;
    const int tid  = threadIdx.x;
    const int lane = tid & 31;
    const int w    = tid >> 5;
    const int wm   = w & 3;        // M group: rows [wm*32, +32)
    const int wn   = w >> 2;       // N group: cols [wn*64, +64)
    const int m0   = blockIdx.x * 128;
    const int which = blockIdx.y;

    float o[2][8][4];
#pragma unroll
    for (int mt = 0; mt < 2; mt++)
#pragma unroll
        for (int nt = 0; nt < 8; nt++)
#pragma unroll
            for (int k = 0; k < 4; k++) o[mt][nt][k] = 0.0f;

    const uint32_t a_row0 = (uint32_t)(wm * 32 + (lane >> 2)) * PJ_RS + (lane & 3) * 8;
    const uint32_t b_base = (uint32_t)(wn * 64 + (lane >> 2)) * PJ_RS + (lane & 3) * 8;

    for (int e0 = 0; e0 < EMB; e0 += 64) {
        __syncthreads();
        // ---- x tile: load raw fp32, cvt to tf32 + pair-permute in regs ----
#pragma unroll
        for (int j = 0; j < 4; j++) {
            int idx = tid + j * 256;
            int row = idx >> 3, c8 = idx & 7;
            const float* src = x + (size_t)(m0 + row) * EMB + e0 + c8 * 8;
            float4 u = *(const float4*)(src);
            float4 v = *(const float4*)(src + 4);
            float s0 = totf32(u.x), s1 = totf32(u.y), s2 = totf32(u.z), s3 = totf32(u.w);
            float s4 = totf32(v.x), s5 = totf32(v.y), s6 = totf32(v.z), s7 = totf32(v.w);
            float* dst = (float*)(smem + PJ_X + row * PJ_RS + c8 * 32);
            *(float4*)(dst)     = make_float4(s0, s4, s1, s5);
            *(float4*)(dst + 4) = make_float4(s2, s6, s3, s7);
        }
        // ---- W tile: straight uint4 copies (perm pre-applied in gmem) ----
#pragma unroll
        for (int j = 0; j < 8; j++) {
            int idx = tid + j * 256;
            int row = idx >> 4, c16 = idx & 15;
            *(uint4*)(smem + PJ_W + row * PJ_RS + c16 * 16) =
                *(const uint4*)(g_Wp + (size_t)(which * HDIM + row) * EMB + e0 + c16 * 4);
        }
        __syncthreads();

#pragma unroll
        for (int st = 0; st < 8; st++) {
            float2 aA0 = *(const float2*)(smem + PJ_X + a_row0 + st * 32);
            float2 aB0 = *(const float2*)(smem + PJ_X + a_row0 + 8 * PJ_RS + st * 32);
            float2 aA1 = *(const float2*)(smem + PJ_X + a_row0 + 16 * PJ_RS + st * 32);
            float2 aB1 = *(const float2*)(smem + PJ_X + a_row0 + 24 * PJ_RS + st * 32);
#pragma unroll
            for (int nt = 0; nt < 8; nt++) {
                float2 b = *(const float2*)(smem + PJ_W + b_base
                                            + (uint32_t)(nt * 8) * PJ_RS + st * 32);
                mma_tf32(o[0][nt][0], o[0][nt][1], o[0][nt][2], o[0][nt][3],
                         aA0.x, aB0.x, aA0.y, aB0.y, b.x, b.y);
                mma_tf32(o[1][nt][0], o[1][nt][1], o[1][nt][2], o[1][nt][3],
                         aA1.x, aB1.x, aA1.y, aB1.y, b.x, b.y);
            }
        }
    }

    // ---- epilogue ----
#pragma unroll
    for (int mt = 0; mt < 2; mt++) {
        const int r0 = m0 + wm * 32 + mt * 16 + (lane >> 2);
        const int r1 = r0 + 8;
        if (which == 2) {
            // V: transpose into g_Vt[b][dim][seq], keys pair-permuted
            const int b0i = r0 >> 12, s0 = r0 & 4095;
            const int b1i = r1 >> 12, s1 = r1 & 4095;
            const int sp0 = (s0 & ~7) + perm8(s0 & 7);
            const int sp1 = (s1 & ~7) + perm8(s1 & 7);
#pragma unroll
            for (int nt = 0; nt < 8; nt++) {
                int col = wn * 64 + nt * 8 + 2 * (lane & 3);
                g_Vt[((size_t)b0i * HDIM + col)     * SEQ + sp0] = totf32(o[mt][nt][0]);
                g_Vt[((size_t)b0i * HDIM + col + 1) * SEQ + sp0] = totf32(o[mt][nt][1]);
                g_Vt[((size_t)b1i * HDIM + col)     * SEQ + sp1] = totf32(o[mt][nt][2]);
                g_Vt[((size_t)b1i * HDIM + col + 1) * SEQ + sp1] = totf32(o[mt][nt][3]);
            }
        } else {
            const float scale = (which == 1) ? (0.03125f * 1.44269504f) : 1.0f;
            float* dst = (which == 1) ? g_Q : g_K;
#pragma unroll
            for (int nt = 0; nt < 8; nt++) {
                int col = wn * 64 + nt * 8 + 2 * (lane & 3);
                int p0 = (col & ~7) + perm8(col & 7);
                int p1 = (col & ~7) + perm8((col & 7) + 1);
                dst[(size_t)r0 * HDIM + p0] = totf32(o[mt][nt][0] * scale);
                dst[(size_t)r0 * HDIM + p1] = totf32(o[mt][nt][1] * scale);
                dst[(size_t)r1 * HDIM + p0] = totf32(o[mt][nt][2] * scale);
                dst[(size_t)r1 * HDIM + p1] = totf32(o[mt][nt][3] * scale);
            }
        }
    }
}

// ===========================================================================
// Flash attention, tf32, 8 warps, FA2 key-split halves IN-CTA + 2-way
// key-parity split ACROSS CTAs (kt ≡ rho mod 2), partials to gmem.
// Pair trick: CTA handles q-tiles p and 63-p -> ~32.5 iters/CTA.
// grid (64, 4): p = bx>>1, rho = bx&1. 256 CTAs, 2 CTAs/SM (106496 B, <=128r).
// Q in smem (no reg hoist), K/V single-buffered (co-CTA hides load latency).
// ===========================================================================
#define AQ_RS  544
#define AK_RS  544
#define AV_RS  288
#define A_Q    0
#define A_K    34816
#define A_V    69632
#define A_SMEM 106496
#define M_INIT (-1e30f)

__global__ __launch_bounds__(256, 2) void attn_mma_kernel()
{
    char* smem = dsmem;
    uint32_t sb = smem_to_u32(smem);
    const int tid  = threadIdx.x;
    const int lane = tid & 31;
    const int w    = tid >> 5;
    const int wq   = w & 3;           // query-row group (16 rows)
    const int nh   = w >> 2;          // key half: 0 -> [0:32), 1 -> [32:64)
    const int b    = blockIdx.y;
    const int pair = blockIdx.x >> 1;
    const int rho  = blockIdx.x & 1;  // key-tile parity
    const int bbase = b * SEQ;

    const int r0 = wq * 16 + (lane >> 2);        // tile-local row (0..63)
    // P-shuffle lane map (C-frag -> A-frag)
    const int pc = lane & 3;
    const int src_lo = (lane & 28) | (pc >> 1);
    const int src_hi = src_lo | 2;
    const int pe = pc & 1;

    // fragment addressing (byte offsets within smem)
    const uint32_t qfo = (uint32_t)(wq * 16 + (lane >> 2)) * AQ_RS + (lane & 3) * 8;
    const uint32_t kfo = A_K + (uint32_t)(nh * 32 + (lane >> 2)) * AK_RS + (lane & 3) * 8;
    const uint32_t vfo = A_V + (uint32_t)(lane >> 2) * AV_RS + (nh * 32) * 4 + (lane & 3) * 8;

    for (int half = 0; half < 2; half++) {
        const int qt = half ? (63 - pair) : pair;

        // ---- stage Q tile into smem (already tf32 + pair-permuted) ----
        __syncthreads();
#pragma unroll
        for (int j = 0; j < 8; j++) {
            int idx = tid + j * 256;               // 0..2047
            int row = idx >> 5, c = idx & 31;
            *(uint4*)(smem + A_Q + (uint32_t)row * AQ_RS + c * 16) =
                *(const uint4*)(g_Q + (size_t)(bbase + qt * 64 + row) * HDIM + c * 4);
        }
        __syncthreads();

        float o[16][4];
#pragma unroll
        for (int t = 0; t < 16; t++)
#pragma unroll
            for (int k = 0; k < 4; k++) o[t][k] = 0.0f;
        float m0 = M_INIT, m1 = M_INIT, l0 = 0.0f, l1 = 0.0f;

        for (int kt = rho; kt <= qt; kt += 2) {
            const int grow = bbase + kt * 64;

            // ---- K and V^T loads (single buffer; trailing barrier freed it) ----
#pragma unroll
            for (int j = 0; j < 8; j++) {
                int idx = tid + j * 256;
                int row = idx >> 5, c = idx & 31;
                CP_ASYNC16(sb + A_K + (uint32_t)row * AK_RS + c * 16,
                           (const void*)(g_K + (size_t)(grow + row) * HDIM + c * 4));
            }
#pragma unroll
            for (int j = 0; j < 8; j++) {
                int idx = tid + j * 256;
                int row = idx >> 4, c = idx & 15;
                CP_ASYNC16(sb + A_V + (uint32_t)row * AV_RS + c * 16,
                           (const void*)(g_Vt + ((size_t)b * HDIM + row) * SEQ
                                         + kt * 64 + c * 4));
            }
            CP_COMMIT();
            CP_WAIT0();
            __syncthreads();

            // ---- S = Q K^T on this warp's 32-key half ----
            float s[4][4];
#pragma unroll
            for (int t = 0; t < 4; t++)
#pragma unroll
                for (int k = 0; k < 4; k++) s[t][k] = 0.0f;

#pragma unroll
            for (int st = 0; st < 16; st++) {
                float2 aA = *(const float2*)(smem + A_Q + qfo + st * 32);
                float2 aB = *(const float2*)(smem + A_Q + qfo + 8 * AQ_RS + st * 32);
#pragma unroll
                for (int np = 0; np < 4; np++) {
                    float2 bb = *(const float2*)(smem + kfo
                                 + (uint32_t)(np * 8) * AK_RS + st * 32);
                    mma_tf32(s[np][0], s[np][1], s[np][2], s[np][3],
                             aA.x, aB.x, aA.y, aB.y, bb.x, bb.y);
                }
            }

            // ---- causal mask on diagonal tile ----
            if (kt == qt) {
                const int rr0 = r0, rr1 = r0 + 8;
#pragma unroll
                for (int nt = 0; nt < 4; nt++) {
                    int c = nh * 32 + nt * 8 + 2 * (lane & 3);
                    if (c     > rr0) s[nt][0] = -INFINITY;
                    if (c + 1 > rr0) s[nt][1] = -INFINITY;
                    if (c     > rr1) s[nt][2] = -INFINITY;
                    if (c + 1 > rr1) s[nt][3] = -INFINITY;
                }
            }

            // ---- online softmax (base-2, independent per key-half) ----
            float rmax0 = -INFINITY, rmax1 = -INFINITY;
#pragma unroll
            for (int nt = 0; nt < 4; nt++) {
                rmax0 = fmaxf(rmax0, fmaxf(s[nt][0], s[nt][1]));
                rmax1 = fmaxf(rmax1, fmaxf(s[nt][2], s[nt][3]));
            }
            rmax0 = fmaxf(rmax0, __shfl_xor_sync(FULLM, rmax0, 1));
            rmax0 = fmaxf(rmax0, __shfl_xor_sync(FULLM, rmax0, 2));
            rmax1 = fmaxf(rmax1, __shfl_xor_sync(FULLM, rmax1, 1));
            rmax1 = fmaxf(rmax1, __shfl_xor_sync(FULLM, rmax1, 2));

            float mn0 = fmaxf(m0, rmax0), mn1 = fmaxf(m1, rmax1);
            float alpha0 = ex2(m0 - mn0), alpha1 = ex2(m1 - mn1);
            m0 = mn0; m1 = mn1;

            float sum0 = 0.0f, sum1 = 0.0f;
#pragma unroll
            for (int nt = 0; nt < 4; nt++) {
                s[nt][0] = ex2(s[nt][0] - mn0);
                s[nt][1] = ex2(s[nt][1] - mn0);
                s[nt][2] = ex2(s[nt][2] - mn1);
                s[nt][3] = ex2(s[nt][3] - mn1);
                sum0 += s[nt][0] + s[nt][1];
                sum1 += s[nt][2] + s[nt][3];
            }
            sum0 += __shfl_xor_sync(FULLM, sum0, 1);
            sum0 += __shfl_xor_sync(FULLM, sum0, 2);
            sum1 += __shfl_xor_sync(FULLM, sum1, 1);
            sum1 += __shfl_xor_sync(FULLM, sum1, 2);
            l0 = l0 * alpha0 + sum0;
            l1 = l1 * alpha1 + sum1;

#pragma unroll
            for (int t = 0; t < 16; t++) {
                o[t][0] *= alpha0; o[t][1] *= alpha0;
                o[t][2] *= alpha1; o[t][3] *= alpha1;
            }

            // ---- O += P V over this warp's 32-key range ----
#pragma unroll
            for (int t = 0; t < 4; t++) {
                float v0 = __shfl_sync(FULLM, s[t][0], src_lo);
                float v1 = __shfl_sync(FULLM, s[t][1], src_lo);
                float v2 = __shfl_sync(FULLM, s[t][2], src_lo);
                float v3 = __shfl_sync(FULLM, s[t][3], src_lo);
                float h0 = __shfl_sync(FULLM, s[t][0], src_hi);
                float h1 = __shfl_sync(FULLM, s[t][1], src_hi);
                float h2 = __shfl_sync(FULLM, s[t][2], src_hi);
                float h3 = __shfl_sync(FULLM, s[t][3], src_hi);
                float pa0 = totf32(pe ? v1 : v0);
                float pa1 = totf32(pe ? v3 : v2);
                float pa2 = totf32(pe ? h1 : h0);
                float pa3 = totf32(pe ? h3 : h2);
#pragma unroll
                for (int nd = 0; nd < 16; nd++) {
                    float2 bb = *(const float2*)(smem + vfo
                                 + (uint32_t)(nd * 8) * AV_RS + t * 32);
                    mma_tf32(o[nd][0], o[nd][1], o[nd][2], o[nd][3],
                             pa0, pa1, pa2, pa3, bb.x, bb.y);
                }
            }

            __syncthreads();   // all smem reads done -> buffer reusable
        }

        // ---- merge key-halves; write UNNORMALIZED partial for this parity ----
        float* O1s = (float*)(smem + A_K);          // [64][128] scratch
        float* M1s = (float*)(smem + A_K + 32768);  // [64]
        float* L1s = M1s + 64;                      // [64]
        if (nh == 1) {
#pragma unroll
            for (int nt = 0; nt < 16; nt++) {
                int col = nt * 8 + 2 * (lane & 3);
                *(float2*)(O1s + (r0)     * 128 + col) = make_float2(o[nt][0], o[nt][1]);
                *(float2*)(O1s + (r0 + 8) * 128 + col) = make_float2(o[nt][2], o[nt][3]);
            }
            if ((lane & 3) == 0) {
                M1s[r0] = m0;  M1s[r0 + 8] = m1;
                L1s[r0] = l0;  L1s[r0 + 8] = l1;
            }
        }
        __syncthreads();
        if (nh == 0) {
            float* Op = rho ? g_O1 : g_O0;
            float m1a = M1s[r0],     l1a = L1s[r0];
            float m1b = M1s[r0 + 8], l1b = L1s[r0 + 8];
            float Ma = fmaxf(m0, m1a), Mb = fmaxf(m1, m1b);
            float b0a = ex2(m0 - Ma),  b1a = ex2(m1a - Ma);
            float b0b = ex2(m1 - Mb),  b1b = ex2(m1b - Mb);
            float La = l0 * b0a + l1a * b1a;
            float Lb = l1 * b0b + l1b * b1b;
            const int gr0 = bbase + qt * 64 + r0;
            const int gr1 = gr0 + 8;
            if ((lane & 3) == 0) {
                g_Mp[rho][gr0] = Ma;  g_Lp[rho][gr0] = La;
                g_Mp[rho][gr1] = Mb;  g_Lp[rho][gr1] = Lb;
            }
#pragma unroll
            for (int nt = 0; nt < 16; nt++) {
                int col = nt * 8 + 2 * (lane & 3);
                float2 p0 = *(const float2*)(O1s + (r0)     * 128 + col);
                float2 p1 = *(const float2*)(O1s + (r0 + 8) * 128 + col);
                *(float2*)(Op + (size_t)gr0 * HDIM + col) = make_float2(
                    o[nt][0] * b0a + p0.x * b1a,
                    o[nt][1] * b0a + p0.y * b1a);
                *(float2*)(Op + (size_t)gr1 * HDIM + col) = make_float2(
                    o[nt][2] * b0b + p1.x * b1b,
                    o[nt][3] * b0b + p1.y * b1b);
            }
        }
    }
}

// ===========================================================================
// Merge the 2 parity partials, float4-vectorized:
// out = sum(O_p * 2^(m_p - M)) / sum(l_p * ...)
// ===========================================================================
__global__ __launch_bounds__(128) void attn_merge_kernel(float* __restrict__ out)
{
    int idx = blockIdx.x * 128 + threadIdx.x;    // one float4 per thread
    int row = idx >> 5;                          // 32 threads per row
    int col = (idx & 31) * 4;
    float m0 = g_Mp[0][row], m1 = g_Mp[1][row];
    float M  = fmaxf(m0, m1);
    float w0 = ex2(m0 - M), w1 = ex2(m1 - M);
    float invL = 1.0f / (g_Lp[0][row] * w0 + g_Lp[1][row] * w1);
    size_t off = (size_t)row * HDIM + col;
    float4 a = *(const float4*)(g_O0 + off);
    float4 bq = *(const float4*)(g_O1 + off);
    *(float4*)(out + off) = make_float4(
        (a.x * w0 + bq.x * w1) * invL,
        (a.y * w0 + bq.y * w1) * invL,
        (a.z * w0 + bq.z * w1) * invL,
        (a.w * w0 + bq.w * w1) * invL);
}

// ---------------------------------------------------------------------------
extern "C" void kernel_launch(void* const* d_in, const int* in_sizes, int n_in,
                              void* d_out, int out_size)
{
    const float* x  = (const float*)d_in[0];
    const float* Wk = (const float*)d_in[1];
    const float* Wq = (const float*)d_in[2];
    const float* Wv = (const float*)d_in[3];
    float* out = (float*)d_out;

    static bool attr_set = false;
    if (!attr_set) {
        cudaFuncSetAttribute(proj_mma_kernel,
                             cudaFuncAttributeMaxDynamicSharedMemorySize, PJ_SMEM);
        cudaFuncSetAttribute(attn_mma_kernel,
                             cudaFuncAttributeMaxDynamicSharedMemorySize, A_SMEM);
        attr_set = true;
    }

    // 1) prep W -> tf32-rounded, pair-permuted (x prep fused into proj)
    wprep_kernel<<<(3 * HDIM * EMB + 255) / 256, 256>>>(Wk, Wq, Wv);

    // 2) Q/K/V projections, tf32, 2D warp tiling, 3 CTAs/SM
    proj_mma_kernel<<<dim3(128, 3), 256, PJ_SMEM>>>(x);

    // 3) causal flash attention: 256 CTAs (pair x 2 key-parities), 2 CTAs/SM
    attn_mma_kernel<<<dim3(64, BATCH), 256, A_SMEM>>>();

    // 4) merge parity partials (float4 per thread)
    attn_merge_kernel<<<BATCH * SEQ * HDIM / 512, 128>>>(out);
}